// round 13
// baseline (speedup 1.0000x reference)
#include <cuda_runtime.h>
#include <cuda_fp16.h>
#include <math.h>
#include <stdint.h>

#define B_   2
#define C_   128
#define H_   96
#define W_   320
#define HW_  30720
#define CQ_  32
#define D_   32
#define NPIX_ (B_*HW_)
#define XEL_  (B_*C_*HW_)
#define NCEL_ (B_*D_*HW_)
#define PH_  98
#define PW_  322

typedef unsigned long long u64;

#define FMA2(d,a,b,c) asm("fma.rn.f32x2 %0, %1, %2, %3;" : "=l"(d) : "l"(a), "l"(b), "l"(c))
#define PACK2(d,lo,hi) asm("mov.b64 %0, {%1, %2};" : "=l"(d) : "r"(__float_as_uint(lo)), "r"(__float_as_uint(hi)))
#define UNPK2(lo,hi,s) do { unsigned _a,_b; asm("mov.b64 {%0, %1}, %2;" : "=r"(_a), "=r"(_b) : "l"(s)); lo=__uint_as_float(_a); hi=__uint_as_float(_b); } while(0)

// ---------------- scratch ----------------
__device__ float  g_sim[NCEL_];
__device__ __align__(16) float g_k[NCEL_];   // NHWC: [b][pix][32]
__device__ __align__(16) __half g_phi[(size_t)B_*PH_*PW_*C_];
__device__ __align__(16) unsigned short g_wH[18][8192];
__device__ float  g_faproj[40];
__device__ float  g_fw[C_];
__device__ float  g_partf[4*480*2];
__device__ float  g_stats[8];
__device__ float  g_cpart[480*128];
__device__ float  g_yscale[B_*C_];
__device__ unsigned g_cnt = 0;

// ---------------- low-level helpers ----------------
__device__ __forceinline__ uint32_t smem_u32(const void* p) {
    uint32_t a;
    asm("{ .reg .u64 t; cvta.to.shared.u64 t, %1; cvt.u32.u64 %0, t; }" : "=r"(a) : "l"(p));
    return a;
}
#define CP16(sm, gp) asm volatile("cp.async.cg.shared.global [%0], [%1], 16;" :: "r"(sm), "l"(gp) : "memory")
#define CP_COMMIT()  asm volatile("cp.async.commit_group;" ::: "memory")
#define CP_WAIT(n)   asm volatile("cp.async.wait_group %0;" :: "n"(n) : "memory")

__device__ __forceinline__ void ldsm_x4(uint32_t* r, uint32_t addr) {
    asm volatile("ldmatrix.sync.aligned.m8n8.x4.shared.b16 {%0,%1,%2,%3}, [%4];"
        : "=r"(r[0]), "=r"(r[1]), "=r"(r[2]), "=r"(r[3]) : "r"(addr));
}
__device__ __forceinline__ void mma16816h(float* d, const uint32_t* a, uint32_t b0, uint32_t b1) {
    asm volatile("mma.sync.aligned.m16n8k16.row.col.f32.f16.f16.f32 "
        "{%0,%1,%2,%3}, {%4,%5,%6,%7}, {%8,%9}, {%0,%1,%2,%3};"
        : "+f"(d[0]), "+f"(d[1]), "+f"(d[2]), "+f"(d[3])
        : "r"(a[0]), "r"(a[1]), "r"(a[2]), "r"(a[3]), "r"(b0), "r"(b1));
}

// ---------------- weight preprocessing ----------------
__global__ void k_prepA(const float* __restrict__ fa_w,
                        const float* __restrict__ ce_w,
                        const float* __restrict__ ce_b,
                        const float* __restrict__ nt_w,
                        const float* __restrict__ nt_b) {
    int t = threadIdx.x;
    if (t < 32) {
        float s = 0.f;
        for (int o = 0; o < C_; o++) s += fa_w[C_ + o] * ce_w[o * D_ + t];
        g_faproj[t] = s;
    } else if (t == 32) {
        float s = 0.f;
        for (int o = 0; o < C_; o++) s += fa_w[C_ + o] * ce_b[o];
        g_faproj[32] = s;
    } else if (t == 33) {
        float s = 0.f;
        for (int c = 0; c < C_; c++) s += fa_w[c] * nt_b[c];
        g_faproj[33] = s;
    } else if (t == 34) {
        float s = 0.f;
        for (int c = 0; c < C_; c++) s += fa_w[c] * nt_w[c];
        g_faproj[34] = s;
    } else if (t >= 64 && t < 64 + C_) {
        int c = t - 64;
        g_fw[c] = fa_w[c] * nt_w[c];
    }
}

__global__ void __launch_bounds__(256) k_prepW(const float* __restrict__ rc_w, int cbase) {
    int it = cbase + blockIdx.x;
    int tap = it % 9, chunk = it / 9;
    for (int idx = threadIdx.x; idx < 8192; idx += 256) {
        int oc = idx >> 6, icl = idx & 63;
        int ic = chunk * 64 + icl;
        float w = rc_w[(oc * C_ + ic) * 9 + tap];
        int pos = oc * 64 + (((icl >> 3) ^ (oc & 7)) << 3) + (icl & 7);
        g_wH[it][pos] = __half_as_ushort(__float2half_rn(w));
    }
}

// ---------------- k projection -> NHWC g_k ----------------
__global__ void __launch_bounds__(256) k_kproj(const float* __restrict__ s_feat,
                                               const float* __restrict__ k_w,
                                               const float* __restrict__ k_b) {
    __shared__ u64 wp[C_][16];
    __shared__ float bsh[CQ_];
    for (int i = threadIdx.x; i < C_ * 16; i += 256) {
        int c = i >> 4, op = i & 15;
        u64 t; PACK2(t, k_w[(2 * op) * C_ + c], k_w[(2 * op + 1) * C_ + c]);
        wp[c][op] = t;
    }
    if (threadIdx.x < CQ_) bsh[threadIdx.x] = k_b[threadIdx.x];
    __syncthreads();

    int idx = blockIdx.x * 256 + threadIdx.x;
    int b = idx / HW_;
    int pix = idx % HW_;
    const float* fp = s_feat + (size_t)b * C_ * HW_ + pix;

    u64 acc[16];
#pragma unroll
    for (int o = 0; o < 16; o++) acc[o] = 0ULL;
#pragma unroll 4
    for (int c = 0; c < C_; c++) {
        float v = fp[(size_t)c * HW_];
        u64 v2; PACK2(v2, v, v);
#pragma unroll
        for (int op = 0; op < 16; op++) FMA2(acc[op], wp[c][op], v2, acc[op]);
    }
    float* dp = g_k + ((size_t)b * HW_ + pix) * 32;
#pragma unroll
    for (int op = 0; op < 8; op++) {
        float l0, h0, l1, h1;
        UNPK2(l0, h0, acc[2 * op]);
        UNPK2(l1, h1, acc[2 * op + 1]);
        float4 v = make_float4(l0 + bsh[4 * op], h0 + bsh[4 * op + 1],
                               l1 + bsh[4 * op + 2], h1 + bsh[4 * op + 3]);
        *reinterpret_cast<float4*>(dp + op * 4) = v;
    }
}

// ---------------- q projection + sim (w-tiled, d-split) + t-stats ----------------
__global__ void __launch_bounds__(128) k_qsim(const float* __restrict__ t_feat,
                                              const float* __restrict__ q_w,
                                              const float* __restrict__ q_b,
                                              const float* __restrict__ disp,
                                              const float* __restrict__ directs) {
    __shared__ u64 wq[C_][16];
    __shared__ float qsh[64][36];
    __shared__ float nq[2][64];
    __shared__ float qinv_s[64];
    __shared__ float dsh[D_];
    __shared__ float r1s[2], r2s[2];

    int hb = blockIdx.x;
    int h = hb / 5, tile = hb % 5;
    int b = blockIdx.y;
    int wl = threadIdx.x & 63, y = threadIdx.x >> 6;
    int tid = threadIdx.x;
    int w = tile * 64 + wl;

    for (int i = tid; i < C_ * 16; i += 128) {
        int c = i >> 4, op = i & 15;
        u64 t; PACK2(t, q_w[(2 * op) * C_ + c], q_w[(2 * op + 1) * C_ + c]);
        wq[c][op] = t;
    }
    if (tid < D_) dsh[tid] = disp[tid];
    __syncthreads();

    // q projection: y half computes op-pairs [y*8, y*8+8)
    float s1 = 0.f, s2 = 0.f;
    {
        const float* tp = t_feat + (size_t)b * C_ * HW_ + h * W_ + w;
        u64 acc[8];
#pragma unroll
        for (int o = 0; o < 8; o++) acc[o] = 0ULL;
#pragma unroll 4
        for (int c = 0; c < C_; c++) {
            float v = tp[(size_t)c * HW_];
            if (y == 0) { s1 += v; s2 += v * v; }
            u64 v2; PACK2(v2, v, v);
#pragma unroll
            for (int o = 0; o < 8; o++) FMA2(acc[o], wq[c][y * 8 + o], v2, acc[o]);
        }
        float n2 = 0.f;
#pragma unroll
        for (int o = 0; o < 8; o++) {
            int op = y * 8 + o;
            float lo, hi; UNPK2(lo, hi, acc[o]);
            lo += q_b[2 * op]; hi += q_b[2 * op + 1];
            qsh[wl][2 * op]     = lo;
            qsh[wl][2 * op + 1] = hi;
            n2 += lo * lo + hi * hi;
        }
        nq[y][wl] = n2;
    }
    __syncthreads();
    if (tid < 64) qinv_s[tid] = 1.f / fmaxf(sqrtf(nq[0][tid] + nq[1][tid]), 1e-12f);
    __syncthreads();

    // t-stats (y==0 covered all channels)
    {
        int lane = tid & 31;
        float a1 = s1, a2 = s2;
#pragma unroll
        for (int o = 16; o > 0; o >>= 1) {
            a1 += __shfl_xor_sync(0xFFFFFFFFu, a1, o);
            a2 += __shfl_xor_sync(0xFFFFFFFFu, a2, o);
        }
        if (y == 0 && lane == 0) { r1s[(tid >> 5) & 1] = a1; r2s[(tid >> 5) & 1] = a2; }
    }
    __syncthreads();
    if (tid == 0) {
        g_partf[((0 * 2 + b) * 480 + h * 5 + tile) * 2 + 0] = r1s[0] + r1s[1];
        g_partf[((0 * 2 + b) * 480 + h * 5 + tile) * 2 + 1] = r2s[0] + r2s[1];
    }

    // load q into regs
    float qr[32];
#pragma unroll
    for (int g4 = 0; g4 < 8; g4++) {
        float4 v = *reinterpret_cast<const float4*>(&qsh[wl][g4 * 4]);
        qr[g4 * 4 + 0] = v.x; qr[g4 * 4 + 1] = v.y; qr[g4 * 4 + 2] = v.z; qr[g4 * 4 + 3] = v.w;
    }
    float invq = qinv_s[wl];
    float dir = directs[b];
    const float* krow = g_k + ((size_t)b * HW_ + h * W_) * 32;
    float* sp = g_sim + (size_t)b * D_ * HW_ + h * W_ + w;

#pragma unroll 2
    for (int j = 0; j < 16; j++) {
        int d = y * 16 + j;
        float pos = (float)w + dsh[d] * dir * (float)(W_ - 1);
        pos = fminf(fmaxf(pos, 0.f), (float)(W_ - 1));
        int x0 = (int)floorf(pos);
        x0 = min(max(x0, 0), W_ - 1);
        int x1 = min(x0 + 1, W_ - 1);
        float t = pos - (float)x0;
        const float4* k0 = reinterpret_cast<const float4*>(krow + (size_t)x0 * 32);
        const float4* k1 = reinterpret_cast<const float4*>(krow + (size_t)x1 * 32);
        float dot = 0.f, kn = 0.f;
#pragma unroll
        for (int g4 = 0; g4 < 8; g4++) {
            float4 a = k0[g4], c = k1[g4];
            float g0 = a.x + t * (c.x - a.x);
            float g1 = a.y + t * (c.y - a.y);
            float g2 = a.z + t * (c.z - a.z);
            float g3 = a.w + t * (c.w - a.w);
            dot += qr[g4 * 4 + 0] * g0 + qr[g4 * 4 + 1] * g1
                 + qr[g4 * 4 + 2] * g2 + qr[g4 * 4 + 3] * g3;
            kn  += g0 * g0 + g1 * g1 + g2 * g2 + g3 * g3;
        }
        sp[(size_t)d * HW_] = dot * invq / fmaxf(sqrtf(kn), 1e-12f);
    }
}

// ---------------- fused cost filter + softmax + c-stats + last-block stats final ----------------
template<int Y>
__device__ __forceinline__ void cost_half(float* cl, const float* __restrict__ base,
                                          const float* __restrict__ wsh,
                                          int h, int w, int lane) {
#pragma unroll
    for (int j = 0; j < 17; j++) {
        const int dd = Y ? (15 + j) : j;
        const int t  = Y ? (j - 1) : j;
        float s0 = 0.f, s1 = 0.f, s2 = 0.f;
#pragma unroll
        for (int r = 0; r < 3; r++) {
            int hh = h + r - 1;
            bool ok = (hh >= 0) && (hh < H_);
            const float* row = base + ((size_t)dd * H_ + hh) * W_;
            float v = ok ? row[w] : 0.f;
            float vm = __shfl_up_sync(0xFFFFFFFFu, v, 1);
            float vp = __shfl_down_sync(0xFFFFFFFFu, v, 1);
            if (lane == 0)  vm = (ok && w > 0)      ? row[w - 1] : 0.f;
            if (lane == 31) vp = (ok && w < W_ - 1) ? row[w + 1] : 0.f;
            s0 += wsh[r * 3 + 0] * vm + wsh[r * 3 + 1] * v + wsh[r * 3 + 2] * vp;
            s1 += wsh[9 + r * 3 + 0] * vm + wsh[9 + r * 3 + 1] * v + wsh[9 + r * 3 + 2] * vp;
            s2 += wsh[18 + r * 3 + 0] * vm + wsh[18 + r * 3 + 1] * v + wsh[18 + r * 3 + 2] * vp;
        }
        if (t + 1 >= 0 && t + 1 < 16 && dd + 1 < D_) cl[t + 1] += s0;
        if (t >= 0 && t < 16)                        cl[t]     += s1;
        if (t - 1 >= 0 && t - 1 < 16)                cl[t - 1] += s2;
    }
}

__global__ void __launch_bounds__(128) k_costsoft(const float* __restrict__ cf_w,
                                                  float* __restrict__ out) {
    __shared__ float wsh[27];
    __shared__ float mx[2][64], sms[2][64];
    __shared__ float r1s[4], r2s[4];
    __shared__ unsigned lastflag;
    __shared__ double d1[128], d2[128];
    int h = blockIdx.x / 5, tile = blockIdx.x % 5, b = blockIdx.y;
    int wl = threadIdx.x, y = threadIdx.y;
    int w = tile * 64 + wl;
    int tid = y * 64 + wl;
    int lane = wl & 31;
    if (tid < 27) wsh[tid] = cf_w[tid];
    __syncthreads();

    const float* base = g_sim + (size_t)b * D_ * HW_;
    float cl[16];
#pragma unroll
    for (int j = 0; j < 16; j++) cl[j] = 0.f;
    if (y == 0) cost_half<0>(cl, base, wsh, h, w, lane);
    else        cost_half<1>(cl, base, wsh, h, w, lane);

    float m = -1e30f;
#pragma unroll
    for (int j = 0; j < 16; j++) m = fmaxf(m, cl[j]);
    mx[y][wl] = m;
    __syncthreads();
    m = fmaxf(mx[0][wl], mx[1][wl]);
    float sum = 0.f;
#pragma unroll
    for (int j = 0; j < 16; j++) { cl[j] = expf(cl[j] - m); sum += cl[j]; }
    sms[y][wl] = sum;
    __syncthreads();
    float invs = 1.f / (sms[0][wl] + sms[1][wl]);

    int d0 = y * 16;
    float* op = out + XEL_ + (size_t)b * D_ * HW_ + (size_t)d0 * HW_ + h * W_ + w;
    float ss1 = 0.f, ss2 = 0.f;
#pragma unroll
    for (int j = 0; j < 16; j++) {
        float v = cl[j] * invs;
        op[(size_t)j * HW_] = v;
        ss1 += v; ss2 += v * v;
    }
#pragma unroll
    for (int o = 16; o > 0; o >>= 1) {
        ss1 += __shfl_xor_sync(0xFFFFFFFFu, ss1, o);
        ss2 += __shfl_xor_sync(0xFFFFFFFFu, ss2, o);
    }
    if (lane == 0) { r1s[tid >> 5] = ss1; r2s[tid >> 5] = ss2; }
    __syncthreads();
    if (tid == 0) {
        g_partf[((1 * 2 + b) * 480 + h * 5 + tile) * 2 + 0] = r1s[0] + r1s[1] + r1s[2] + r1s[3];
        g_partf[((1 * 2 + b) * 480 + h * 5 + tile) * 2 + 1] = r2s[0] + r2s[1] + r2s[2] + r2s[3];
        __threadfence();
        unsigned old = atomicAdd(&g_cnt, 1u);
        lastflag = (old == 960u - 1u) ? 1u : 0u;
    }
    __syncthreads();
    if (lastflag) {
        for (int wb = 0; wb < 4; wb++) {
            int which = wb >> 1;
            double s1 = 0.0, s2 = 0.0;
            for (int i = tid; i < 480; i += 128) {
                s1 += (double)__ldcg(&g_partf[(wb * 480 + i) * 2 + 0]);
                s2 += (double)__ldcg(&g_partf[(wb * 480 + i) * 2 + 1]);
            }
            d1[tid] = s1; d2[tid] = s2;
            __syncthreads();
            for (int s = 64; s > 0; s >>= 1) {
                if (tid < s) { d1[tid] += d1[tid + s]; d2[tid] += d2[tid + s]; }
                __syncthreads();
            }
            if (tid == 0) {
                double N = which ? (double)(D_ * HW_) : (double)(C_ * HW_);
                double mu  = d1[0] / N;
                double var = d2[0] / N - mu * mu;
                g_stats[wb * 2 + 0] = (float)mu;
                g_stats[wb * 2 + 1] = (float)(1.0 / sqrt(var + 1e-5));
            }
            __syncthreads();
        }
        if (tid == 0) g_cnt = 0;
    }
}

// ---------------- fuse: GEMM-tiled cost-embed + gating (R11 256-thread version) ----------------
#define FS_CN    0
#define FS_CEP   17408
#define FS_FUSED 0
#define FS_ALPHA 34816
#define FS_NCW   35328
#define FS_NCB   35456
#define FS_PROJ  35584
#define FS_FW    35744
#define FS_NTW   36256
#define FS_NTB   36768
#define FS_CEB   37280
#define FUSE_SMEM 37888

__global__ void __launch_bounds__(256) k_fuse(const float* __restrict__ out_base,
                                              const float* __restrict__ t_feat,
                                              const float* __restrict__ nt_w,
                                              const float* __restrict__ nt_b,
                                              const float* __restrict__ nc_w,
                                              const float* __restrict__ nc_b,
                                              const float* __restrict__ ce_w,
                                              const float* __restrict__ ce_b,
                                              const float* __restrict__ fa_b) {
    extern __shared__ __align__(16) char sm[];
    float* cn_s   = reinterpret_cast<float*>(sm + FS_CN);
    float* cep_s  = reinterpret_cast<float*>(sm + FS_CEP);
    __half* fu_s  = reinterpret_cast<__half*>(sm + FS_FUSED);
    float* alp_s  = reinterpret_cast<float*>(sm + FS_ALPHA);
    float* ncw_s  = reinterpret_cast<float*>(sm + FS_NCW);
    float* ncb_s  = reinterpret_cast<float*>(sm + FS_NCB);
    float* proj_s = reinterpret_cast<float*>(sm + FS_PROJ);
    float* fw_s   = reinterpret_cast<float*>(sm + FS_FW);
    float* ntw_s  = reinterpret_cast<float*>(sm + FS_NTW);
    float* ntb_s  = reinterpret_cast<float*>(sm + FS_NTB);
    float* ceb_s  = reinterpret_cast<float*>(sm + FS_CEB);

    int tid = threadIdx.x;
    {
        const float4* cw4 = reinterpret_cast<const float4*>(ce_w);
#pragma unroll
        for (int j = 0; j < 4; j++) {
            int i4 = tid + j * 256;
            float4 v = cw4[i4];
            int base = i4 * 4;
            int oc = base >> 5, d = base & 31;
            cep_s[(d + 0) * 128 + oc] = v.x;
            cep_s[(d + 1) * 128 + oc] = v.y;
            cep_s[(d + 2) * 128 + oc] = v.z;
            cep_s[(d + 3) * 128 + oc] = v.w;
        }
    }
    if (tid < C_) {
        ntw_s[tid] = nt_w[tid];
        ntb_s[tid] = nt_b[tid];
        ceb_s[tid] = ce_b[tid];
        fw_s[tid]  = g_fw[tid];
    }
    if (tid < D_) { ncw_s[tid] = nc_w[tid]; ncb_s[tid] = nc_b[tid]; }
    if (tid >= 128 && tid < 168) proj_s[tid - 128] = g_faproj[tid - 128];
    __syncthreads();

    int blk = blockIdx.x;
    int b = (blk >= 240) ? 1 : 0;
    int pix0 = (blk * 128) % HW_;
    float mu_t = g_stats[b * 2 + 0], inv_t = g_stats[b * 2 + 1];
    float mu_c = g_stats[4 + b * 2 + 0], inv_c = g_stats[4 + b * 2 + 1];

    // phase 1: cn + alpha (2 threads/pixel)
    {
        int pixl = tid >> 1, half = tid & 1;
        int pixg = pix0 + pixl;
        const float* ncp = out_base + XEL_ + (size_t)b * D_ * HW_ + pixg;
        float alin = half ? 0.f
                          : (fa_b[0] + proj_s[32] + proj_s[33] - inv_t * mu_t * proj_s[34]);
#pragma unroll
        for (int j = 0; j < 16; j++) {
            int d = half * 16 + j;
            float v = (ncp[(size_t)d * HW_] - mu_c) * inv_c * ncw_s[d] + ncb_s[d];
            cn_s[d * 136 + pixl] = v;
            alin += proj_s[d] * v;
        }
        const float* tp = t_feat + (size_t)b * C_ * HW_ + pixg;
        float dotft = 0.f;
#pragma unroll 4
        for (int cc = 0; cc < 64; cc++) {
            int c = half * 64 + cc;
            dotft += fw_s[c] * tp[(size_t)c * HW_];
        }
        alin += inv_t * dotft;
        alin += __shfl_xor_sync(0xFFFFFFFFu, alin, 1);
        if (half == 0) alp_s[pixl] = 1.f / (1.f + expf(-alin));
    }
    __syncthreads();

    // phase 2: GEMM cf = ceb + ce_w @ cn (8x8 micro-tiles)
    int tx = tid & 15, ty = tid >> 4;
    int oc0 = ty * 8, px0 = tx * 8;
    float acc[8][8];
#pragma unroll
    for (int o = 0; o < 8; o++) {
        float cb = ceb_s[oc0 + o];
#pragma unroll
        for (int p = 0; p < 8; p++) acc[o][p] = cb;
    }
#pragma unroll 4
    for (int d = 0; d < D_; d++) {
        float4 a0 = *reinterpret_cast<const float4*>(&cep_s[d * 128 + oc0]);
        float4 a1 = *reinterpret_cast<const float4*>(&cep_s[d * 128 + oc0 + 4]);
        float4 b0 = *reinterpret_cast<const float4*>(&cn_s[d * 136 + px0]);
        float4 b1 = *reinterpret_cast<const float4*>(&cn_s[d * 136 + px0 + 4]);
        float av[8] = {a0.x, a0.y, a0.z, a0.w, a1.x, a1.y, a1.z, a1.w};
        float bv[8] = {b0.x, b0.y, b0.z, b0.w, b1.x, b1.y, b1.z, b1.w};
#pragma unroll
        for (int o = 0; o < 8; o++)
#pragma unroll
            for (int p = 0; p < 8; p++) acc[o][p] += av[o] * bv[p];
    }
    __syncthreads();

    // phase 3: tv + gate -> fu_s fp16
#pragma unroll
    for (int o = 0; o < 8; o++) {
        int oc = oc0 + o;
        const float* trow = t_feat + (size_t)b * C_ * HW_ + (size_t)oc * HW_ + pix0 + px0;
        float4 t0 = *reinterpret_cast<const float4*>(trow);
        float4 t1 = *reinterpret_cast<const float4*>(trow + 4);
        float tvv[8] = {t0.x, t0.y, t0.z, t0.w, t1.x, t1.y, t1.z, t1.w};
        float wv = ntw_s[oc], bb = ntb_s[oc];
        unsigned hq[4];
#pragma unroll
        for (int p = 0; p < 8; p++) {
            float tv = (tvv[p] - mu_t) * inv_t * wv + bb;
            float al = alp_s[px0 + p];
            float f = al * tv + (1.f - al) * acc[o][p];
            unsigned short us = __half_as_ushort(__float2half_rn(f));
            if ((p & 1) == 0) hq[p >> 1] = us;
            else hq[p >> 1] |= ((unsigned)us << 16);
        }
        *reinterpret_cast<uint4*>(&fu_s[oc * 136 + px0]) = make_uint4(hq[0], hq[1], hq[2], hq[3]);
    }
    __syncthreads();

    // phase 4: write padded NHWC + borders
#pragma unroll
    for (int j = 0; j < 8; j++) {
        int item = tid + j * 256;
        int oc8 = item >> 7;
        int pixl = item & 127;
        int pixg = pix0 + pixl;
        int h = pixg / W_, w = pixg % W_;
        unsigned hq[4];
#pragma unroll
        for (int o = 0; o < 8; o++) {
            unsigned short us = __half_as_ushort(fu_s[(oc8 * 8 + o) * 136 + pixl]);
            if ((o & 1) == 0) hq[o >> 1] = us;
            else hq[o >> 1] |= ((unsigned)us << 16);
        }
        uint4 val = make_uint4(hq[0], hq[1], hq[2], hq[3]);
        size_t pbase = ((size_t)(b * PH_ + h + 1) * PW_ + (w + 1)) * C_ + oc8 * 8;
        *reinterpret_cast<uint4*>(&g_phi[pbase]) = val;
        bool top = (h == 1), bot = (h == H_ - 2);
        bool lef = (w == 1), rig = (w == W_ - 2);
        if (top | bot | lef | rig) {
            const size_t ROW2 = 2 * (size_t)PW_ * C_;
            if (top) *reinterpret_cast<uint4*>(&g_phi[pbase - ROW2]) = val;
            if (bot) *reinterpret_cast<uint4*>(&g_phi[pbase + ROW2]) = val;
            if (lef) *reinterpret_cast<uint4*>(&g_phi[pbase - 2 * C_]) = val;
            if (rig) *reinterpret_cast<uint4*>(&g_phi[pbase + 2 * C_]) = val;
            if (top && lef) *reinterpret_cast<uint4*>(&g_phi[pbase - ROW2 - 2 * C_]) = val;
            if (top && rig) *reinterpret_cast<uint4*>(&g_phi[pbase - ROW2 + 2 * C_]) = val;
            if (bot && lef) *reinterpret_cast<uint4*>(&g_phi[pbase + ROW2 - 2 * C_]) = val;
            if (bot && rig) *reinterpret_cast<uint4*>(&g_phi[pbase + ROW2 + 2 * C_]) = val;
        }
    }
}

// ---------------- mma.sync implicit-GEMM conv (18 iters, K=64) ----------------
#define A_HI  0
#define B_OFF 23040
#define CONV_SMEM 55808

__global__ void __launch_bounds__(256, 2) k_conv_mma(const float* __restrict__ rc_b,
                                                     float* __restrict__ out) {
    extern __shared__ __align__(128) char smem[];
    uint32_t sb = smem_u32(smem);
    int tid = threadIdx.x, lane = tid & 31, wid = tid >> 5;
    int warp_m = wid & 3, warp_n = wid >> 2;

    int bx = blockIdx.x % 20;
    int by = (blockIdx.x / 20) % 12;
    int b  = blockIdx.x / 240;
    int h0 = by * 8, w0 = bx * 16;
    size_t pbase = ((size_t)(b * PH_ + h0) * PW_ + w0) * C_;

    int m_loc = lane & 15, khalf_a = lane >> 4;
    int rA[2], cA[2];
#pragma unroll
    for (int mt = 0; mt < 2; mt++) {
        int m_abs = warp_m * 32 + mt * 16 + m_loc;
        rA[mt] = m_abs >> 4;
        cA[mt] = m_abs & 15;
    }
    int subB = lane >> 3;
    int nl = (lane & 7) + ((subB & 2) << 2);
    int khalf_b = subB & 1;
    uint32_t bRow[4]; int bSw[4];
#pragma unroll
    for (int nb4 = 0; nb4 < 4; nb4++) {
        int oc = warp_n * 64 + nb4 * 16 + nl;
        bRow[nb4] = (uint32_t)oc * 128;
        bSw[nb4]  = oc & 7;
    }

    float acc[2][8][4];
#pragma unroll
    for (int mt = 0; mt < 2; mt++)
#pragma unroll
        for (int n = 0; n < 8; n++)
#pragma unroll
            for (int e = 0; e < 4; e++) acc[mt][n][e] = 0.f;

    {
        const uint4* s0 = reinterpret_cast<const uint4*>(g_wH[0]);
#pragma unroll
        for (int j = 0; j < 4; j++) {
            int idx = tid + j * 256;
            CP16(sb + B_OFF + idx * 16, s0 + idx);
        }
        CP_COMMIT();
    }

    for (int it = 0; it < 18; it++) {
        int chunk = it / 9, tap = it % 9, buf = it & 1;
        int dy = tap / 3, dx = tap % 3;
        __syncthreads();

        if (tap == 0) {
            for (int i = tid; i < 1440; i += 256) {
                int row = i >> 3, ch = i & 7;
                int pr = row / 18, pc = row % 18;
                size_t g = pbase + ((size_t)pr * PW_ + pc) * C_ + chunk * 64 + ch * 8;
                uint32_t so = (uint32_t)row * 128 + ((ch ^ (row & 7)) << 4);
                CP16(sb + A_HI + so, &g_phi[g]);
            }
            CP_COMMIT();
        }
        if (it + 1 < 18) {
            const uint4* s0 = reinterpret_cast<const uint4*>(g_wH[it + 1]);
            uint32_t d0 = sb + B_OFF + (buf ^ 1) * 16384;
#pragma unroll
            for (int j = 0; j < 4; j++) {
                int idx = tid + j * 256;
                CP16(d0 + idx * 16, s0 + idx);
            }
        }
        CP_COMMIT();
        CP_WAIT(1);
        __syncthreads();

        uint32_t bbase = sb + B_OFF + buf * 16384;
        int rowA[2], swA[2];
#pragma unroll
        for (int mt = 0; mt < 2; mt++) {
            rowA[mt] = (rA[mt] + dy) * 18 + cA[mt] + dx;
            swA[mt]  = rowA[mt] & 7;
        }

#pragma unroll
        for (int k16 = 0; k16 < 4; k16++) {
            int chA = k16 * 2 + khalf_a;
            int chB = k16 * 2 + khalf_b;
            uint32_t ah[2][4];
#pragma unroll
            for (int mt = 0; mt < 2; mt++) {
                uint32_t off = (uint32_t)rowA[mt] * 128 + ((chA ^ swA[mt]) << 4);
                ldsm_x4(ah[mt], sb + A_HI + off);
            }
            uint32_t bh[4][4];
#pragma unroll
            for (int nb4 = 0; nb4 < 4; nb4++) {
                uint32_t off = bRow[nb4] + ((chB ^ bSw[nb4]) << 4);
                ldsm_x4(bh[nb4], bbase + off);
            }
#pragma unroll
            for (int mt = 0; mt < 2; mt++) {
#pragma unroll
                for (int nb4 = 0; nb4 < 4; nb4++) {
#pragma unroll
                    for (int half = 0; half < 2; half++) {
                        int n = nb4 * 2 + half;
                        mma16816h(acc[mt][n], ah[mt], bh[nb4][half * 2], bh[nb4][half * 2 + 1]);
                    }
                }
            }
        }
    }

    float* sf = reinterpret_cast<float*>(smem);
    int rbase = lane >> 2, cpair = (lane & 3) * 2;
#pragma unroll
    for (int p = 0; p < 2; p++) {
        __syncthreads();
        if (warp_n == p) {
#pragma unroll
            for (int mt = 0; mt < 2; mt++)
#pragma unroll
                for (int nbl = 0; nbl < 8; nbl++)
#pragma unroll
                    for (int e = 0; e < 4; e++) {
                        int m   = warp_m * 32 + mt * 16 + rbase + ((e >> 1) << 3);
                        int ocl = nbl * 8 + cpair + (e & 1);
                        sf[ocl * 132 + m] = acc[mt][nbl][e];
                    }
        }
        __syncthreads();
#pragma unroll
        for (int j = 0; j < 8; j++) {
            int idx = tid + j * 256;
            int ocl = idx >> 5, q = idx & 31;
            int r = q >> 2, cc = (q & 3) * 4;
            float4 v = *reinterpret_cast<const float4*>(&sf[ocl * 132 + r * 16 + cc]);
            int oc = p * 64 + ocl;
            float bias = rc_b[oc];
            v.x += bias; v.y += bias; v.z += bias; v.w += bias;
            *reinterpret_cast<float4*>(&out[(size_t)(b * C_ + oc) * HW_ + (h0 + r) * W_ + w0 + cc]) = v;
            float s = (v.x + v.y) + (v.z + v.w);
#pragma unroll
            for (int o = 16; o > 0; o >>= 1) s += __shfl_xor_sync(0xFFFFFFFFu, s, o);
            if (lane == 0) g_cpart[(size_t)blockIdx.x * 128 + oc] = s;
        }
    }
}

// ---------------- squeeze-excite ----------------
__global__ void __launch_bounds__(1024) k_se2(const float* __restrict__ se_w1,
                                              const float* __restrict__ se_w2) {
    __shared__ float part[4][256];
    __shared__ float mean_s[256];
    __shared__ float y1s[16];
    int tid = threadIdx.x;
    int q = tid >> 8, bc = tid & 255;
    int b = bc >> 7, c = bc & 127;
    float s = 0.f;
    for (int t = q * 60; t < q * 60 + 60; t++)
        s += g_cpart[(size_t)(b * 240 + t) * 128 + c];
    part[q][bc] = s;
    __syncthreads();
    if (tid < 256) {
        float m = part[0][tid] + part[1][tid] + part[2][tid] + part[3][tid];
        mean_s[tid] = m / (float)HW_;
    }
    __syncthreads();
    if (tid < 16) {
        int bb = tid / 8, j = tid % 8;
        float s2 = 0.f;
        for (int cc = 0; cc < C_; cc++) s2 += mean_s[bb * 128 + cc] * se_w1[j * C_ + cc];
        y1s[tid] = fmaxf(s2, 0.f);
    }
    __syncthreads();
    if (tid < 256) {
        int bb = tid >> 7, cc = tid & 127;
        float s3 = 0.f;
#pragma unroll
        for (int j = 0; j < 8; j++) s3 += y1s[bb * 8 + j] * se_w2[cc * 8 + j];
        g_yscale[tid] = 1.f / (1.f + expf(-s3));
    }
}

__global__ void __launch_bounds__(256) k_elu(float* __restrict__ out) {
    int idx4 = blockIdx.x * 256 + threadIdx.x;
    float ysc = g_yscale[(idx4 * 4) / HW_];
    float4 v = reinterpret_cast<float4*>(out)[idx4];
    v.x *= ysc; v.y *= ysc; v.z *= ysc; v.w *= ysc;
    v.x = v.x > 0.f ? v.x : expm1f(v.x);
    v.y = v.y > 0.f ? v.y : expm1f(v.y);
    v.z = v.z > 0.f ? v.z : expm1f(v.z);
    v.w = v.w > 0.f ? v.w : expm1f(v.w);
    reinterpret_cast<float4*>(out)[idx4] = v;
}

// ---------------- launch ----------------
extern "C" void kernel_launch(void* const* d_in, const int* in_sizes, int n_in,
                              void* d_out, int out_size) {
    const float* t_feat  = (const float*)d_in[0];
    const float* s_feat  = (const float*)d_in[1];
    const float* directs = (const float*)d_in[2];
    const float* disp    = (const float*)d_in[3];
    const float* q_w     = (const float*)d_in[4];
    const float* q_b     = (const float*)d_in[5];
    const float* k_w     = (const float*)d_in[6];
    const float* k_b     = (const float*)d_in[7];
    const float* cf_w    = (const float*)d_in[8];
    const float* nt_w    = (const float*)d_in[10];
    const float* nt_b    = (const float*)d_in[11];
    const float* nc_w    = (const float*)d_in[12];
    const float* nc_b    = (const float*)d_in[13];
    const float* ce_w    = (const float*)d_in[14];
    const float* ce_b    = (const float*)d_in[15];
    const float* fa_w    = (const float*)d_in[16];
    const float* fa_b    = (const float*)d_in[17];
    const float* rc_w    = (const float*)d_in[18];
    const float* rc_b    = (const float*)d_in[19];
    const float* se_w1   = (const float*)d_in[20];
    const float* se_w2   = (const float*)d_in[21];
    float* out = (float*)d_out;

    cudaFuncSetAttribute(k_conv_mma, cudaFuncAttributeMaxDynamicSharedMemorySize, CONV_SMEM);
    cudaFuncSetAttribute(k_fuse, cudaFuncAttributeMaxDynamicSharedMemorySize, FUSE_SMEM);

    k_prepA<<<1, 256>>>(fa_w, ce_w, ce_b, nt_w, nt_b);
    k_prepW<<<9, 256>>>(rc_w, 0);
    k_prepW<<<9, 256>>>(rc_w, 9);
    k_kproj<<<NPIX_ / 256, 256>>>(s_feat, k_w, k_b);
    k_qsim<<<dim3(H_ * 5, B_), 128>>>(t_feat, q_w, q_b, disp, directs);
    k_costsoft<<<dim3(H_ * 5, B_), dim3(64, 2)>>>(cf_w, out);
    k_fuse<<<480, 256, FUSE_SMEM>>>(out, t_feat, nt_w, nt_b, nc_w, nc_b, ce_w, ce_b, fa_b);
    k_conv_mma<<<480, 256, CONV_SMEM>>>(rc_b, out);
    k_se2<<<1, 1024>>>(se_w1, se_w2);
    k_elu<<<XEL_ / 1024, 256>>>(out);
}

// round 14
// speedup vs baseline: 1.3200x; 1.3200x over previous
#include <cuda_runtime.h>
#include <cuda_fp16.h>
#include <math.h>
#include <stdint.h>

#define B_   2
#define C_   128
#define H_   96
#define W_   320
#define HW_  30720
#define CQ_  32
#define D_   32
#define NPIX_ (B_*HW_)
#define XEL_  (B_*C_*HW_)
#define NCEL_ (B_*D_*HW_)
#define PH_  98
#define PW_  322

typedef unsigned long long u64;

#define PACK2(d,lo,hi) asm("mov.b64 %0, {%1, %2};" : "=l"(d) : "r"(__float_as_uint(lo)), "r"(__float_as_uint(hi)))

// ---------------- scratch ----------------
__device__ float  g_sim[NCEL_];
__device__ __align__(16) float g_qk[(size_t)NPIX_*64];   // NHWC: [b*HW+pix][64] (q 0-31 | k 32-63)
__device__ __align__(16) __half g_phi[(size_t)B_*PH_*PW_*C_];
__device__ __align__(16) unsigned short g_wH[18][8192];
__device__ float  g_faproj[40];
__device__ float  g_fw[C_];
__device__ float  g_partf[4*480*2];
__device__ float  g_stats[8];
__device__ float  g_cpart[480*128];
__device__ float  g_yscale[B_*C_];
__device__ unsigned g_cnt = 0;

// ---------------- low-level helpers ----------------
__device__ __forceinline__ uint32_t smem_u32(const void* p) {
    uint32_t a;
    asm("{ .reg .u64 t; cvta.to.shared.u64 t, %1; cvt.u32.u64 %0, t; }" : "=r"(a) : "l"(p));
    return a;
}
#define CP16(sm, gp) asm volatile("cp.async.cg.shared.global [%0], [%1], 16;" :: "r"(sm), "l"(gp) : "memory")
#define CP_COMMIT()  asm volatile("cp.async.commit_group;" ::: "memory")
#define CP_WAIT(n)   asm volatile("cp.async.wait_group %0;" :: "n"(n) : "memory")

__device__ __forceinline__ void ldsm_x4(uint32_t* r, uint32_t addr) {
    asm volatile("ldmatrix.sync.aligned.m8n8.x4.shared.b16 {%0,%1,%2,%3}, [%4];"
        : "=r"(r[0]), "=r"(r[1]), "=r"(r[2]), "=r"(r[3]) : "r"(addr));
}
__device__ __forceinline__ void mma16816h(float* d, const uint32_t* a, uint32_t b0, uint32_t b1) {
    asm volatile("mma.sync.aligned.m16n8k16.row.col.f32.f16.f16.f32 "
        "{%0,%1,%2,%3}, {%4,%5,%6,%7}, {%8,%9}, {%0,%1,%2,%3};"
        : "+f"(d[0]), "+f"(d[1]), "+f"(d[2]), "+f"(d[3])
        : "r"(a[0]), "r"(a[1]), "r"(a[2]), "r"(a[3]), "r"(b0), "r"(b1));
}

// ---------------- combined weight preprocessing ----------------
__global__ void __launch_bounds__(256) k_prepall(const float* __restrict__ fa_w,
                                                 const float* __restrict__ ce_w,
                                                 const float* __restrict__ ce_b,
                                                 const float* __restrict__ nt_w,
                                                 const float* __restrict__ nt_b,
                                                 const float* __restrict__ rc_w) {
    int blk = blockIdx.x;
    if (blk == 0) {
        int t = threadIdx.x;
        if (t < 32) {
            float s = 0.f;
            for (int o = 0; o < C_; o++) s += fa_w[C_ + o] * ce_w[o * D_ + t];
            g_faproj[t] = s;
        } else if (t == 32) {
            float s = 0.f;
            for (int o = 0; o < C_; o++) s += fa_w[C_ + o] * ce_b[o];
            g_faproj[32] = s;
        } else if (t == 33) {
            float s = 0.f;
            for (int c = 0; c < C_; c++) s += fa_w[c] * nt_b[c];
            g_faproj[33] = s;
        } else if (t == 34) {
            float s = 0.f;
            for (int c = 0; c < C_; c++) s += fa_w[c] * nt_w[c];
            g_faproj[34] = s;
        } else if (t >= 64 && t < 64 + C_) {
            int c = t - 64;
            g_fw[c] = fa_w[c] * nt_w[c];
        }
    } else {
        int it = blk - 1;
        int tap = it % 9, chunk = it / 9;
        for (int idx = threadIdx.x; idx < 8192; idx += 256) {
            int oc = idx >> 6, icl = idx & 63;
            int ic = chunk * 64 + icl;
            float w = rc_w[(oc * C_ + ic) * 9 + tap];
            int pos = oc * 64 + (((icl >> 3) ^ (oc & 7)) << 3) + (icl & 7);
            g_wH[it][pos] = __half_as_ushort(__float2half_rn(w));
        }
    }
}

// ---------------- q+k projection as tiled GEMM + t-stats ----------------
#define QK_WS  0                       // float [128][68]  34816
#define QK_INT 34816                   // float [16][132]   8448
#define QK_INS 43264                   // float [16][132]   8448
#define QK_SMEM 51712

__global__ void __launch_bounds__(256) k_qkproj(const float* __restrict__ t_feat,
                                                const float* __restrict__ s_feat,
                                                const float* __restrict__ q_w,
                                                const float* __restrict__ q_b,
                                                const float* __restrict__ k_w,
                                                const float* __restrict__ k_b) {
    extern __shared__ __align__(16) char sm[];
    float* w_s  = reinterpret_cast<float*>(sm + QK_WS);
    float* it_s = reinterpret_cast<float*>(sm + QK_INT);
    float* is_s = reinterpret_cast<float*>(sm + QK_INS);
    __shared__ float rs1[8], rs2[8];

    int tid = threadIdx.x;
    int blk = blockIdx.x;
    int b = blk / 240, pslot = blk % 240;
    int pix0 = pslot * 128;

    for (int i = tid; i < 4096; i += 256) {
        int oc = i >> 7, c = i & 127;
        w_s[c * 68 + oc] = q_w[i];
    }
    for (int i = tid; i < 4096; i += 256) {
        int oc = i >> 7, c = i & 127;
        w_s[c * 68 + 32 + oc] = k_w[i];
    }

    int tx = tid & 15, ty = tid >> 4;
    int px0 = tx * 8, oc0 = ty * 4;
    bool isK = (ty >= 8);

    float acc[4][8];
#pragma unroll
    for (int o = 0; o < 4; o++)
#pragma unroll
        for (int p = 0; p < 8; p++) acc[o][p] = 0.f;
    float s1 = 0.f, s2 = 0.f;

    for (int cc = 0; cc < 8; cc++) {
        __syncthreads();
#pragma unroll
        for (int j = 0; j < 8; j++) {
            int i = tid + j * 256;
            int c = i >> 7, pix = i & 127;
            size_t off = ((size_t)(b * C_ + cc * 16 + c)) * HW_ + pix0 + pix;
            float v = t_feat[off];
            it_s[c * 132 + pix] = v;
            s1 += v; s2 += v * v;
            is_s[c * 132 + pix] = s_feat[off];
        }
        __syncthreads();
        const float* in = isK ? is_s : it_s;
#pragma unroll
        for (int c = 0; c < 16; c++) {
            float4 wv = *reinterpret_cast<const float4*>(&w_s[(cc * 16 + c) * 68 + oc0]);
            float4 b0 = *reinterpret_cast<const float4*>(&in[c * 132 + px0]);
            float4 b1 = *reinterpret_cast<const float4*>(&in[c * 132 + px0 + 4]);
            float bv[8] = {b0.x, b0.y, b0.z, b0.w, b1.x, b1.y, b1.z, b1.w};
            float av[4] = {wv.x, wv.y, wv.z, wv.w};
#pragma unroll
            for (int o = 0; o < 4; o++)
#pragma unroll
                for (int p = 0; p < 8; p++) acc[o][p] += av[o] * bv[p];
        }
    }

    float bias[4];
#pragma unroll
    for (int o = 0; o < 4; o++) {
        int oc = oc0 + o;
        bias[o] = (oc < 32) ? q_b[oc] : k_b[oc - 32];
    }
#pragma unroll
    for (int p = 0; p < 8; p++) {
        float4 v = make_float4(acc[0][p] + bias[0], acc[1][p] + bias[1],
                               acc[2][p] + bias[2], acc[3][p] + bias[3]);
        *reinterpret_cast<float4*>(&g_qk[((size_t)(b * HW_) + pix0 + px0 + p) * 64 + oc0]) = v;
    }

    // t-stats block reduce (each t element staged exactly once)
    int lane = tid & 31;
#pragma unroll
    for (int o = 16; o > 0; o >>= 1) {
        s1 += __shfl_xor_sync(0xFFFFFFFFu, s1, o);
        s2 += __shfl_xor_sync(0xFFFFFFFFu, s2, o);
    }
    if (lane == 0) { rs1[tid >> 5] = s1; rs2[tid >> 5] = s2; }
    __syncthreads();
    if (tid == 0) {
        float t1 = 0.f, t2 = 0.f;
#pragma unroll
        for (int i = 0; i < 8; i++) { t1 += rs1[i]; t2 += rs2[i]; }
        g_partf[((0 * 2 + b) * 480 + pslot) * 2 + 0] = t1;
        g_partf[((0 * 2 + b) * 480 + pslot) * 2 + 1] = t2;
    }
}

// ---------------- sim: stage k-row in smem, q from regs ----------------
#define SIM_SMEM 41216   // ksh [32][321] + dsh

__global__ void __launch_bounds__(160) k_sim(const float* __restrict__ disp,
                                             const float* __restrict__ directs) {
    extern __shared__ __align__(16) char sm[];
    float* ksh = reinterpret_cast<float*>(sm);            // [c][321]
    float* dsh = reinterpret_cast<float*>(sm + 32 * 321 * 4);
    int h = blockIdx.x >> 1, wh = blockIdx.x & 1;
    int b = blockIdx.y;
    int tid = threadIdx.x;
    if (tid < D_) dsh[tid] = disp[tid];

    const float* qkrow = g_qk + ((size_t)b * HW_ + h * W_) * 64;
    for (int i = tid; i < W_ * 8; i += 160) {
        int pix = i >> 3, c4 = i & 7;
        float4 v = *reinterpret_cast<const float4*>(&qkrow[(size_t)pix * 64 + 32 + c4 * 4]);
        ksh[(c4 * 4 + 0) * 321 + pix] = v.x;
        ksh[(c4 * 4 + 1) * 321 + pix] = v.y;
        ksh[(c4 * 4 + 2) * 321 + pix] = v.z;
        ksh[(c4 * 4 + 3) * 321 + pix] = v.w;
    }
    int w = wh * 160 + tid;
    float qr[32];
    float n2 = 0.f;
#pragma unroll
    for (int g4 = 0; g4 < 8; g4++) {
        float4 v = *reinterpret_cast<const float4*>(&qkrow[(size_t)w * 64 + g4 * 4]);
        qr[g4 * 4 + 0] = v.x; qr[g4 * 4 + 1] = v.y;
        qr[g4 * 4 + 2] = v.z; qr[g4 * 4 + 3] = v.w;
        n2 += v.x * v.x + v.y * v.y + v.z * v.z + v.w * v.w;
    }
    float invq = 1.f / fmaxf(sqrtf(n2), 1e-12f);
    float dir = directs[b];
    __syncthreads();

    float* sp = g_sim + (size_t)b * D_ * HW_ + h * W_ + w;
#pragma unroll 2
    for (int d = 0; d < D_; d++) {
        float pos = (float)w + dsh[d] * dir * (float)(W_ - 1);
        pos = fminf(fmaxf(pos, 0.f), (float)(W_ - 1));
        int x0 = (int)floorf(pos);
        x0 = min(max(x0, 0), W_ - 1);
        int x1 = min(x0 + 1, W_ - 1);
        float t = pos - (float)x0;
        float dot = 0.f, kn = 0.f;
#pragma unroll
        for (int c = 0; c < CQ_; c++) {
            float a = ksh[c * 321 + x0];
            float g = a + t * (ksh[c * 321 + x1] - a);
            dot += qr[c] * g;
            kn += g * g;
        }
        sp[(size_t)d * HW_] = dot * invq / fmaxf(sqrtf(kn), 1e-12f);
    }
}

// ---------------- fused cost filter + softmax + c-stats + last-block stats final ----------------
template<int Y>
__device__ __forceinline__ void cost_half(float* cl, const float* __restrict__ base,
                                          const float* __restrict__ wsh,
                                          int h, int w, int lane) {
#pragma unroll
    for (int j = 0; j < 17; j++) {
        const int dd = Y ? (15 + j) : j;
        const int t  = Y ? (j - 1) : j;
        float s0 = 0.f, s1 = 0.f, s2 = 0.f;
#pragma unroll
        for (int r = 0; r < 3; r++) {
            int hh = h + r - 1;
            bool ok = (hh >= 0) && (hh < H_);
            const float* row = base + ((size_t)dd * H_ + hh) * W_;
            float v = ok ? row[w] : 0.f;
            float vm = __shfl_up_sync(0xFFFFFFFFu, v, 1);
            float vp = __shfl_down_sync(0xFFFFFFFFu, v, 1);
            if (lane == 0)  vm = (ok && w > 0)      ? row[w - 1] : 0.f;
            if (lane == 31) vp = (ok && w < W_ - 1) ? row[w + 1] : 0.f;
            s0 += wsh[r * 3 + 0] * vm + wsh[r * 3 + 1] * v + wsh[r * 3 + 2] * vp;
            s1 += wsh[9 + r * 3 + 0] * vm + wsh[9 + r * 3 + 1] * v + wsh[9 + r * 3 + 2] * vp;
            s2 += wsh[18 + r * 3 + 0] * vm + wsh[18 + r * 3 + 1] * v + wsh[18 + r * 3 + 2] * vp;
        }
        if (t + 1 >= 0 && t + 1 < 16 && dd + 1 < D_) cl[t + 1] += s0;
        if (t >= 0 && t < 16)                        cl[t]     += s1;
        if (t - 1 >= 0 && t - 1 < 16)                cl[t - 1] += s2;
    }
}

__global__ void __launch_bounds__(128) k_costsoft(const float* __restrict__ cf_w,
                                                  float* __restrict__ out) {
    __shared__ float wsh[27];
    __shared__ float mx[2][64], sms[2][64];
    __shared__ float r1s[4], r2s[4];
    __shared__ unsigned lastflag;
    __shared__ double d1[128], d2[128];
    int h = blockIdx.x / 5, tile = blockIdx.x % 5, b = blockIdx.y;
    int wl = threadIdx.x, y = threadIdx.y;
    int w = tile * 64 + wl;
    int tid = y * 64 + wl;
    int lane = wl & 31;
    if (tid < 27) wsh[tid] = cf_w[tid];
    __syncthreads();

    const float* base = g_sim + (size_t)b * D_ * HW_;
    float cl[16];
#pragma unroll
    for (int j = 0; j < 16; j++) cl[j] = 0.f;
    if (y == 0) cost_half<0>(cl, base, wsh, h, w, lane);
    else        cost_half<1>(cl, base, wsh, h, w, lane);

    float m = -1e30f;
#pragma unroll
    for (int j = 0; j < 16; j++) m = fmaxf(m, cl[j]);
    mx[y][wl] = m;
    __syncthreads();
    m = fmaxf(mx[0][wl], mx[1][wl]);
    float sum = 0.f;
#pragma unroll
    for (int j = 0; j < 16; j++) { cl[j] = expf(cl[j] - m); sum += cl[j]; }
    sms[y][wl] = sum;
    __syncthreads();
    float invs = 1.f / (sms[0][wl] + sms[1][wl]);

    int d0 = y * 16;
    float* op = out + XEL_ + (size_t)b * D_ * HW_ + (size_t)d0 * HW_ + h * W_ + w;
    float ss1 = 0.f, ss2 = 0.f;
#pragma unroll
    for (int j = 0; j < 16; j++) {
        float v = cl[j] * invs;
        op[(size_t)j * HW_] = v;
        ss1 += v; ss2 += v * v;
    }
#pragma unroll
    for (int o = 16; o > 0; o >>= 1) {
        ss1 += __shfl_xor_sync(0xFFFFFFFFu, ss1, o);
        ss2 += __shfl_xor_sync(0xFFFFFFFFu, ss2, o);
    }
    if (lane == 0) { r1s[tid >> 5] = ss1; r2s[tid >> 5] = ss2; }
    __syncthreads();
    if (tid == 0) {
        g_partf[((1 * 2 + b) * 480 + h * 5 + tile) * 2 + 0] = r1s[0] + r1s[1] + r1s[2] + r1s[3];
        g_partf[((1 * 2 + b) * 480 + h * 5 + tile) * 2 + 1] = r2s[0] + r2s[1] + r2s[2] + r2s[3];
        __threadfence();
        unsigned old = atomicAdd(&g_cnt, 1u);
        lastflag = (old == 960u - 1u) ? 1u : 0u;
    }
    __syncthreads();
    if (lastflag) {
        for (int wb = 0; wb < 4; wb++) {
            int which = wb >> 1;
            int n = which ? 480 : 240;
            double s1 = 0.0, s2 = 0.0;
            for (int i = tid; i < n; i += 128) {
                s1 += (double)__ldcg(&g_partf[(wb * 480 + i) * 2 + 0]);
                s2 += (double)__ldcg(&g_partf[(wb * 480 + i) * 2 + 1]);
            }
            d1[tid] = s1; d2[tid] = s2;
            __syncthreads();
            for (int s = 64; s > 0; s >>= 1) {
                if (tid < s) { d1[tid] += d1[tid + s]; d2[tid] += d2[tid + s]; }
                __syncthreads();
            }
            if (tid == 0) {
                double N = which ? (double)(D_ * HW_) : (double)(C_ * HW_);
                double mu  = d1[0] / N;
                double var = d2[0] / N - mu * mu;
                g_stats[wb * 2 + 0] = (float)mu;
                g_stats[wb * 2 + 1] = (float)(1.0 / sqrt(var + 1e-5));
            }
            __syncthreads();
        }
        if (tid == 0) g_cnt = 0;
    }
}

// ---------------- fuse: GEMM-tiled cost-embed + gating (R11 version) ----------------
#define FS_CN    0
#define FS_CEP   17408
#define FS_FUSED 0
#define FS_ALPHA 34816
#define FS_NCW   35328
#define FS_NCB   35456
#define FS_PROJ  35584
#define FS_FW    35744
#define FS_NTW   36256
#define FS_NTB   36768
#define FS_CEB   37280
#define FUSE_SMEM 37888

__global__ void __launch_bounds__(256) k_fuse(const float* __restrict__ out_base,
                                              const float* __restrict__ t_feat,
                                              const float* __restrict__ nt_w,
                                              const float* __restrict__ nt_b,
                                              const float* __restrict__ nc_w,
                                              const float* __restrict__ nc_b,
                                              const float* __restrict__ ce_w,
                                              const float* __restrict__ ce_b,
                                              const float* __restrict__ fa_b) {
    extern __shared__ __align__(16) char sm[];
    float* cn_s   = reinterpret_cast<float*>(sm + FS_CN);
    float* cep_s  = reinterpret_cast<float*>(sm + FS_CEP);
    __half* fu_s  = reinterpret_cast<__half*>(sm + FS_FUSED);
    float* alp_s  = reinterpret_cast<float*>(sm + FS_ALPHA);
    float* ncw_s  = reinterpret_cast<float*>(sm + FS_NCW);
    float* ncb_s  = reinterpret_cast<float*>(sm + FS_NCB);
    float* proj_s = reinterpret_cast<float*>(sm + FS_PROJ);
    float* fw_s   = reinterpret_cast<float*>(sm + FS_FW);
    float* ntw_s  = reinterpret_cast<float*>(sm + FS_NTW);
    float* ntb_s  = reinterpret_cast<float*>(sm + FS_NTB);
    float* ceb_s  = reinterpret_cast<float*>(sm + FS_CEB);

    int tid = threadIdx.x;
    {
        const float4* cw4 = reinterpret_cast<const float4*>(ce_w);
#pragma unroll
        for (int j = 0; j < 4; j++) {
            int i4 = tid + j * 256;
            float4 v = cw4[i4];
            int base = i4 * 4;
            int oc = base >> 5, d = base & 31;
            cep_s[(d + 0) * 128 + oc] = v.x;
            cep_s[(d + 1) * 128 + oc] = v.y;
            cep_s[(d + 2) * 128 + oc] = v.z;
            cep_s[(d + 3) * 128 + oc] = v.w;
        }
    }
    if (tid < C_) {
        ntw_s[tid] = nt_w[tid];
        ntb_s[tid] = nt_b[tid];
        ceb_s[tid] = ce_b[tid];
        fw_s[tid]  = g_fw[tid];
    }
    if (tid < D_) { ncw_s[tid] = nc_w[tid]; ncb_s[tid] = nc_b[tid]; }
    if (tid >= 128 && tid < 168) proj_s[tid - 128] = g_faproj[tid - 128];
    __syncthreads();

    int blk = blockIdx.x;
    int b = (blk >= 240) ? 1 : 0;
    int pix0 = (blk * 128) % HW_;
    float mu_t = g_stats[b * 2 + 0], inv_t = g_stats[b * 2 + 1];
    float mu_c = g_stats[4 + b * 2 + 0], inv_c = g_stats[4 + b * 2 + 1];

    {
        int pixl = tid >> 1, half = tid & 1;
        int pixg = pix0 + pixl;
        const float* ncp = out_base + XEL_ + (size_t)b * D_ * HW_ + pixg;
        float alin = half ? 0.f
                          : (fa_b[0] + proj_s[32] + proj_s[33] - inv_t * mu_t * proj_s[34]);
#pragma unroll
        for (int j = 0; j < 16; j++) {
            int d = half * 16 + j;
            float v = (ncp[(size_t)d * HW_] - mu_c) * inv_c * ncw_s[d] + ncb_s[d];
            cn_s[d * 136 + pixl] = v;
            alin += proj_s[d] * v;
        }
        const float* tp = t_feat + (size_t)b * C_ * HW_ + pixg;
        float dotft = 0.f;
#pragma unroll 4
        for (int cc = 0; cc < 64; cc++) {
            int c = half * 64 + cc;
            dotft += fw_s[c] * tp[(size_t)c * HW_];
        }
        alin += inv_t * dotft;
        alin += __shfl_xor_sync(0xFFFFFFFFu, alin, 1);
        if (half == 0) alp_s[pixl] = 1.f / (1.f + expf(-alin));
    }
    __syncthreads();

    int tx = tid & 15, ty = tid >> 4;
    int oc0 = ty * 8, px0 = tx * 8;
    float acc[8][8];
#pragma unroll
    for (int o = 0; o < 8; o++) {
        float cb = ceb_s[oc0 + o];
#pragma unroll
        for (int p = 0; p < 8; p++) acc[o][p] = cb;
    }
#pragma unroll 4
    for (int d = 0; d < D_; d++) {
        float4 a0 = *reinterpret_cast<const float4*>(&cep_s[d * 128 + oc0]);
        float4 a1 = *reinterpret_cast<const float4*>(&cep_s[d * 128 + oc0 + 4]);
        float4 b0 = *reinterpret_cast<const float4*>(&cn_s[d * 136 + px0]);
        float4 b1 = *reinterpret_cast<const float4*>(&cn_s[d * 136 + px0 + 4]);
        float av[8] = {a0.x, a0.y, a0.z, a0.w, a1.x, a1.y, a1.z, a1.w};
        float bv[8] = {b0.x, b0.y, b0.z, b0.w, b1.x, b1.y, b1.z, b1.w};
#pragma unroll
        for (int o = 0; o < 8; o++)
#pragma unroll
            for (int p = 0; p < 8; p++) acc[o][p] += av[o] * bv[p];
    }
    __syncthreads();

#pragma unroll
    for (int o = 0; o < 8; o++) {
        int oc = oc0 + o;
        const float* trow = t_feat + (size_t)b * C_ * HW_ + (size_t)oc * HW_ + pix0 + px0;
        float4 t0 = *reinterpret_cast<const float4*>(trow);
        float4 t1 = *reinterpret_cast<const float4*>(trow + 4);
        float tvv[8] = {t0.x, t0.y, t0.z, t0.w, t1.x, t1.y, t1.z, t1.w};
        float wv = ntw_s[oc], bb = ntb_s[oc];
        unsigned hq[4];
#pragma unroll
        for (int p = 0; p < 8; p++) {
            float tv = (tvv[p] - mu_t) * inv_t * wv + bb;
            float al = alp_s[px0 + p];
            float f = al * tv + (1.f - al) * acc[o][p];
            unsigned short us = __half_as_ushort(__float2half_rn(f));
            if ((p & 1) == 0) hq[p >> 1] = us;
            else hq[p >> 1] |= ((unsigned)us << 16);
        }
        *reinterpret_cast<uint4*>(&fu_s[oc * 136 + px0]) = make_uint4(hq[0], hq[1], hq[2], hq[3]);
    }
    __syncthreads();

#pragma unroll
    for (int j = 0; j < 8; j++) {
        int item = tid + j * 256;
        int oc8 = item >> 7;
        int pixl = item & 127;
        int pixg = pix0 + pixl;
        int h = pixg / W_, w = pixg % W_;
        unsigned hq[4];
#pragma unroll
        for (int o = 0; o < 8; o++) {
            unsigned short us = __half_as_ushort(fu_s[(oc8 * 8 + o) * 136 + pixl]);
            if ((o & 1) == 0) hq[o >> 1] = us;
            else hq[o >> 1] |= ((unsigned)us << 16);
        }
        uint4 val = make_uint4(hq[0], hq[1], hq[2], hq[3]);
        size_t pbase = ((size_t)(b * PH_ + h + 1) * PW_ + (w + 1)) * C_ + oc8 * 8;
        *reinterpret_cast<uint4*>(&g_phi[pbase]) = val;
        bool top = (h == 1), bot = (h == H_ - 2);
        bool lef = (w == 1), rig = (w == W_ - 2);
        if (top | bot | lef | rig) {
            const size_t ROW2 = 2 * (size_t)PW_ * C_;
            if (top) *reinterpret_cast<uint4*>(&g_phi[pbase - ROW2]) = val;
            if (bot) *reinterpret_cast<uint4*>(&g_phi[pbase + ROW2]) = val;
            if (lef) *reinterpret_cast<uint4*>(&g_phi[pbase - 2 * C_]) = val;
            if (rig) *reinterpret_cast<uint4*>(&g_phi[pbase + 2 * C_]) = val;
            if (top && lef) *reinterpret_cast<uint4*>(&g_phi[pbase - ROW2 - 2 * C_]) = val;
            if (top && rig) *reinterpret_cast<uint4*>(&g_phi[pbase - ROW2 + 2 * C_]) = val;
            if (bot && lef) *reinterpret_cast<uint4*>(&g_phi[pbase + ROW2 - 2 * C_]) = val;
            if (bot && rig) *reinterpret_cast<uint4*>(&g_phi[pbase + ROW2 + 2 * C_]) = val;
        }
    }
}

// ---------------- mma.sync implicit-GEMM conv (18 iters, K=64) ----------------
#define A_HI  0
#define B_OFF 23040
#define CONV_SMEM 55808

__global__ void __launch_bounds__(256, 2) k_conv_mma(const float* __restrict__ rc_b,
                                                     float* __restrict__ out) {
    extern __shared__ __align__(128) char smem[];
    uint32_t sb = smem_u32(smem);
    int tid = threadIdx.x, lane = tid & 31, wid = tid >> 5;
    int warp_m = wid & 3, warp_n = wid >> 2;

    int bx = blockIdx.x % 20;
    int by = (blockIdx.x / 20) % 12;
    int b  = blockIdx.x / 240;
    int h0 = by * 8, w0 = bx * 16;
    size_t pbase = ((size_t)(b * PH_ + h0) * PW_ + w0) * C_;

    int m_loc = lane & 15, khalf_a = lane >> 4;
    int rA[2], cA[2];
#pragma unroll
    for (int mt = 0; mt < 2; mt++) {
        int m_abs = warp_m * 32 + mt * 16 + m_loc;
        rA[mt] = m_abs >> 4;
        cA[mt] = m_abs & 15;
    }
    int subB = lane >> 3;
    int nl = (lane & 7) + ((subB & 2) << 2);
    int khalf_b = subB & 1;
    uint32_t bRow[4]; int bSw[4];
#pragma unroll
    for (int nb4 = 0; nb4 < 4; nb4++) {
        int oc = warp_n * 64 + nb4 * 16 + nl;
        bRow[nb4] = (uint32_t)oc * 128;
        bSw[nb4]  = oc & 7;
    }

    float acc[2][8][4];
#pragma unroll
    for (int mt = 0; mt < 2; mt++)
#pragma unroll
        for (int n = 0; n < 8; n++)
#pragma unroll
            for (int e = 0; e < 4; e++) acc[mt][n][e] = 0.f;

    {
        const uint4* s0 = reinterpret_cast<const uint4*>(g_wH[0]);
#pragma unroll
        for (int j = 0; j < 4; j++) {
            int idx = tid + j * 256;
            CP16(sb + B_OFF + idx * 16, s0 + idx);
        }
        CP_COMMIT();
    }

    for (int it = 0; it < 18; it++) {
        int chunk = it / 9, tap = it % 9, buf = it & 1;
        int dy = tap / 3, dx = tap % 3;
        __syncthreads();

        if (tap == 0) {
            for (int i = tid; i < 1440; i += 256) {
                int row = i >> 3, ch = i & 7;
                int pr = row / 18, pc = row % 18;
                size_t g = pbase + ((size_t)pr * PW_ + pc) * C_ + chunk * 64 + ch * 8;
                uint32_t so = (uint32_t)row * 128 + ((ch ^ (row & 7)) << 4);
                CP16(sb + A_HI + so, &g_phi[g]);
            }
            CP_COMMIT();
        }
        if (it + 1 < 18) {
            const uint4* s0 = reinterpret_cast<const uint4*>(g_wH[it + 1]);
            uint32_t d0 = sb + B_OFF + (buf ^ 1) * 16384;
#pragma unroll
            for (int j = 0; j < 4; j++) {
                int idx = tid + j * 256;
                CP16(d0 + idx * 16, s0 + idx);
            }
        }
        CP_COMMIT();
        CP_WAIT(1);
        __syncthreads();

        uint32_t bbase = sb + B_OFF + buf * 16384;
        int rowA[2], swA[2];
#pragma unroll
        for (int mt = 0; mt < 2; mt++) {
            rowA[mt] = (rA[mt] + dy) * 18 + cA[mt] + dx;
            swA[mt]  = rowA[mt] & 7;
        }

#pragma unroll
        for (int k16 = 0; k16 < 4; k16++) {
            int chA = k16 * 2 + khalf_a;
            int chB = k16 * 2 + khalf_b;
            uint32_t ah[2][4];
#pragma unroll
            for (int mt = 0; mt < 2; mt++) {
                uint32_t off = (uint32_t)rowA[mt] * 128 + ((chA ^ swA[mt]) << 4);
                ldsm_x4(ah[mt], sb + A_HI + off);
            }
            uint32_t bh[4][4];
#pragma unroll
            for (int nb4 = 0; nb4 < 4; nb4++) {
                uint32_t off = bRow[nb4] + ((chB ^ bSw[nb4]) << 4);
                ldsm_x4(bh[nb4], bbase + off);
            }
#pragma unroll
            for (int mt = 0; mt < 2; mt++) {
#pragma unroll
                for (int nb4 = 0; nb4 < 4; nb4++) {
#pragma unroll
                    for (int half = 0; half < 2; half++) {
                        int n = nb4 * 2 + half;
                        mma16816h(acc[mt][n], ah[mt], bh[nb4][half * 2], bh[nb4][half * 2 + 1]);
                    }
                }
            }
        }
    }

    float* sf = reinterpret_cast<float*>(smem);
    int rbase = lane >> 2, cpair = (lane & 3) * 2;
#pragma unroll
    for (int p = 0; p < 2; p++) {
        __syncthreads();
        if (warp_n == p) {
#pragma unroll
            for (int mt = 0; mt < 2; mt++)
#pragma unroll
                for (int nbl = 0; nbl < 8; nbl++)
#pragma unroll
                    for (int e = 0; e < 4; e++) {
                        int m   = warp_m * 32 + mt * 16 + rbase + ((e >> 1) << 3);
                        int ocl = nbl * 8 + cpair + (e & 1);
                        sf[ocl * 132 + m] = acc[mt][nbl][e];
                    }
        }
        __syncthreads();
#pragma unroll
        for (int j = 0; j < 8; j++) {
            int idx = tid + j * 256;
            int ocl = idx >> 5, q = idx & 31;
            int r = q >> 2, cc = (q & 3) * 4;
            float4 v = *reinterpret_cast<const float4*>(&sf[ocl * 132 + r * 16 + cc]);
            int oc = p * 64 + ocl;
            float bias = rc_b[oc];
            v.x += bias; v.y += bias; v.z += bias; v.w += bias;
            *reinterpret_cast<float4*>(&out[(size_t)(b * C_ + oc) * HW_ + (h0 + r) * W_ + w0 + cc]) = v;
            float s = (v.x + v.y) + (v.z + v.w);
#pragma unroll
            for (int o = 16; o > 0; o >>= 1) s += __shfl_xor_sync(0xFFFFFFFFu, s, o);
            if (lane == 0) g_cpart[(size_t)blockIdx.x * 128 + oc] = s;
        }
    }
}

// ---------------- squeeze-excite ----------------
__global__ void __launch_bounds__(1024) k_se2(const float* __restrict__ se_w1,
                                              const float* __restrict__ se_w2) {
    __shared__ float part[4][256];
    __shared__ float mean_s[256];
    __shared__ float y1s[16];
    int tid = threadIdx.x;
    int q = tid >> 8, bc = tid & 255;
    int b = bc >> 7, c = bc & 127;
    float s = 0.f;
    for (int t = q * 60; t < q * 60 + 60; t++)
        s += g_cpart[(size_t)(b * 240 + t) * 128 + c];
    part[q][bc] = s;
    __syncthreads();
    if (tid < 256) {
        float m = part[0][tid] + part[1][tid] + part[2][tid] + part[3][tid];
        mean_s[tid] = m / (float)HW_;
    }
    __syncthreads();
    if (tid < 16) {
        int bb = tid / 8, j = tid % 8;
        float s2 = 0.f;
        for (int cc = 0; cc < C_; cc++) s2 += mean_s[bb * 128 + cc] * se_w1[j * C_ + cc];
        y1s[tid] = fmaxf(s2, 0.f);
    }
    __syncthreads();
    if (tid < 256) {
        int bb = tid >> 7, cc = tid & 127;
        float s3 = 0.f;
#pragma unroll
        for (int j = 0; j < 8; j++) s3 += y1s[bb * 8 + j] * se_w2[cc * 8 + j];
        g_yscale[tid] = 1.f / (1.f + expf(-s3));
    }
}

__global__ void __launch_bounds__(256) k_elu(float* __restrict__ out) {
    int idx4 = blockIdx.x * 256 + threadIdx.x;
    float ysc = g_yscale[(idx4 * 4) / HW_];
    float4 v = reinterpret_cast<float4*>(out)[idx4];
    v.x *= ysc; v.y *= ysc; v.z *= ysc; v.w *= ysc;
    v.x = v.x > 0.f ? v.x : expm1f(v.x);
    v.y = v.y > 0.f ? v.y : expm1f(v.y);
    v.z = v.z > 0.f ? v.z : expm1f(v.z);
    v.w = v.w > 0.f ? v.w : expm1f(v.w);
    reinterpret_cast<float4*>(out)[idx4] = v;
}

// ---------------- launch ----------------
extern "C" void kernel_launch(void* const* d_in, const int* in_sizes, int n_in,
                              void* d_out, int out_size) {
    const float* t_feat  = (const float*)d_in[0];
    const float* s_feat  = (const float*)d_in[1];
    const float* directs = (const float*)d_in[2];
    const float* disp    = (const float*)d_in[3];
    const float* q_w     = (const float*)d_in[4];
    const float* q_b     = (const float*)d_in[5];
    const float* k_w     = (const float*)d_in[6];
    const float* k_b     = (const float*)d_in[7];
    const float* cf_w    = (const float*)d_in[8];
    const float* nt_w    = (const float*)d_in[10];
    const float* nt_b    = (const float*)d_in[11];
    const float* nc_w    = (const float*)d_in[12];
    const float* nc_b    = (const float*)d_in[13];
    const float* ce_w    = (const float*)d_in[14];
    const float* ce_b    = (const float*)d_in[15];
    const float* fa_w    = (const float*)d_in[16];
    const float* fa_b    = (const float*)d_in[17];
    const float* rc_w    = (const float*)d_in[18];
    const float* rc_b    = (const float*)d_in[19];
    const float* se_w1   = (const float*)d_in[20];
    const float* se_w2   = (const float*)d_in[21];
    float* out = (float*)d_out;

    cudaFuncSetAttribute(k_conv_mma, cudaFuncAttributeMaxDynamicSharedMemorySize, CONV_SMEM);
    cudaFuncSetAttribute(k_fuse, cudaFuncAttributeMaxDynamicSharedMemorySize, FUSE_SMEM);
    cudaFuncSetAttribute(k_qkproj, cudaFuncAttributeMaxDynamicSharedMemorySize, QK_SMEM);
    cudaFuncSetAttribute(k_sim, cudaFuncAttributeMaxDynamicSharedMemorySize, SIM_SMEM);

    k_prepall<<<19, 256>>>(fa_w, ce_w, ce_b, nt_w, nt_b, rc_w);
    k_qkproj<<<480, 256, QK_SMEM>>>(t_feat, s_feat, q_w, q_b, k_w, k_b);
    k_sim<<<dim3(H_ * 2, B_), 160, SIM_SMEM>>>(disp, directs);
    k_costsoft<<<dim3(H_ * 5, B_), dim3(64, 2)>>>(cf_w, out);
    k_fuse<<<480, 256, FUSE_SMEM>>>(out, t_feat, nt_w, nt_b, nc_w, nc_b, ce_w, ce_b, fa_b);
    k_conv_mma<<<480, 256, CONV_SMEM>>>(rc_b, out);
    k_se2<<<1, 1024>>>(se_w1, se_w2);
    k_elu<<<XEL_ / 1024, 256>>>(out);
}

// round 15
// speedup vs baseline: 1.4267x; 1.0808x over previous
#include <cuda_runtime.h>
#include <cuda_fp16.h>
#include <math.h>
#include <stdint.h>

#define B_   2
#define C_   128
#define H_   96
#define W_   320
#define HW_  30720
#define CQ_  32
#define D_   32
#define NPIX_ (B_*HW_)
#define XEL_  (B_*C_*HW_)
#define NCEL_ (B_*D_*HW_)
#define PH_  98
#define PW_  322

typedef unsigned long long u64;

#define FMA2(d,a,b,c) asm("fma.rn.f32x2 %0, %1, %2, %3;" : "=l"(d) : "l"(a), "l"(b), "l"(c))
#define PACK2(d,lo,hi) asm("mov.b64 %0, {%1, %2};" : "=l"(d) : "r"(__float_as_uint(lo)), "r"(__float_as_uint(hi)))
#define UNPK2(lo,hi,s) do { unsigned _a,_b; asm("mov.b64 {%0, %1}, %2;" : "=r"(_a), "=r"(_b) : "l"(s)); lo=__uint_as_float(_a); hi=__uint_as_float(_b); } while(0)

// ---------------- scratch ----------------
__device__ float  g_sim[NCEL_];
__device__ __align__(16) __half g_phi[(size_t)B_*PH_*PW_*C_];
__device__ __align__(16) unsigned short g_wH[18][8192];
__device__ float  g_faproj[40];
__device__ float  g_fw[C_];
__device__ float  g_partf[4*480*2];
__device__ float  g_stats[8];
__device__ float  g_cpart[480*128];
__device__ float  g_yscale[B_*C_];

// ---------------- low-level helpers ----------------
__device__ __forceinline__ uint32_t smem_u32(const void* p) {
    uint32_t a;
    asm("{ .reg .u64 t; cvta.to.shared.u64 t, %1; cvt.u32.u64 %0, t; }" : "=r"(a) : "l"(p));
    return a;
}
#define CP16(sm, gp) asm volatile("cp.async.cg.shared.global [%0], [%1], 16;" :: "r"(sm), "l"(gp) : "memory")
#define CP_COMMIT()  asm volatile("cp.async.commit_group;" ::: "memory")
#define CP_WAIT(n)   asm volatile("cp.async.wait_group %0;" :: "n"(n) : "memory")

__device__ __forceinline__ void ldsm_x4(uint32_t* r, uint32_t addr) {
    asm volatile("ldmatrix.sync.aligned.m8n8.x4.shared.b16 {%0,%1,%2,%3}, [%4];"
        : "=r"(r[0]), "=r"(r[1]), "=r"(r[2]), "=r"(r[3]) : "r"(addr));
}
__device__ __forceinline__ void mma16816h(float* d, const uint32_t* a, uint32_t b0, uint32_t b1) {
    asm volatile("mma.sync.aligned.m16n8k16.row.col.f32.f16.f16.f32 "
        "{%0,%1,%2,%3}, {%4,%5,%6,%7}, {%8,%9}, {%0,%1,%2,%3};"
        : "+f"(d[0]), "+f"(d[1]), "+f"(d[2]), "+f"(d[3])
        : "r"(a[0]), "r"(a[1]), "r"(a[2]), "r"(a[3]), "r"(b0), "r"(b1));
}

// ---------------- combined weight preprocessing ----------------
__global__ void __launch_bounds__(256) k_prepall(const float* __restrict__ fa_w,
                                                 const float* __restrict__ ce_w,
                                                 const float* __restrict__ ce_b,
                                                 const float* __restrict__ nt_w,
                                                 const float* __restrict__ nt_b,
                                                 const float* __restrict__ rc_w) {
    int blk = blockIdx.x;
    if (blk == 0) {
        int t = threadIdx.x;
        if (t < 32) {
            float s = 0.f;
            for (int o = 0; o < C_; o++) s += fa_w[C_ + o] * ce_w[o * D_ + t];
            g_faproj[t] = s;
        } else if (t == 32) {
            float s = 0.f;
            for (int o = 0; o < C_; o++) s += fa_w[C_ + o] * ce_b[o];
            g_faproj[32] = s;
        } else if (t == 33) {
            float s = 0.f;
            for (int c = 0; c < C_; c++) s += fa_w[c] * nt_b[c];
            g_faproj[33] = s;
        } else if (t == 34) {
            float s = 0.f;
            for (int c = 0; c < C_; c++) s += fa_w[c] * nt_w[c];
            g_faproj[34] = s;
        } else if (t >= 64 && t < 64 + C_) {
            int c = t - 64;
            g_fw[c] = fa_w[c] * nt_w[c];
        }
    } else {
        int it = blk - 1;
        int tap = it % 9, chunk = it / 9;
        for (int idx = threadIdx.x; idx < 8192; idx += 256) {
            int oc = idx >> 6, icl = idx & 63;
            int ic = chunk * 64 + icl;
            float w = rc_w[(oc * C_ + ic) * 9 + tap];
            int pos = oc * 64 + (((icl >> 3) ^ (oc & 7)) << 3) + (icl & 7);
            g_wH[it][pos] = __half_as_ushort(__float2half_rn(w));
        }
    }
}

// ---------------- fused q/k projection + warp + cosine sim + t-stats ----------------
#define SQ_KSH 0
#define SQ_WQ  40960
#define SQ_WK  57344
#define SQ_BQ  73728
#define SQ_BK  73856
#define SQ_R1  73984
#define SQ_R2  74032
#define SIMQK_SMEM 74112

__global__ void __launch_bounds__(W_) k_simqk(const float* __restrict__ t_feat,
                                              const float* __restrict__ s_feat,
                                              const float* __restrict__ q_w,
                                              const float* __restrict__ q_b,
                                              const float* __restrict__ k_w,
                                              const float* __restrict__ k_b,
                                              const float* __restrict__ disp,
                                              const float* __restrict__ directs) {
    extern __shared__ __align__(16) char sm[];
    float* ksh = reinterpret_cast<float*>(sm + SQ_KSH);
    u64*   wq  = reinterpret_cast<u64*>(sm + SQ_WQ);
    u64*   wk  = reinterpret_cast<u64*>(sm + SQ_WK);
    float* bq  = reinterpret_cast<float*>(sm + SQ_BQ);
    float* bk  = reinterpret_cast<float*>(sm + SQ_BK);
    float* r1  = reinterpret_cast<float*>(sm + SQ_R1);
    float* r2  = reinterpret_cast<float*>(sm + SQ_R2);

    int h = blockIdx.x, b = blockIdx.y;
    int w = threadIdx.x, lane = w & 31, wrp = w >> 5;

    for (int i = threadIdx.x; i < C_ * 16; i += W_) {
        int c = i >> 4, op = i & 15;
        u64 t;
        PACK2(t, q_w[(2 * op) * C_ + c], q_w[(2 * op + 1) * C_ + c]);
        wq[i] = t;
        PACK2(t, k_w[(2 * op) * C_ + c], k_w[(2 * op + 1) * C_ + c]);
        wk[i] = t;
    }
    if (threadIdx.x < CQ_) { bq[threadIdx.x] = q_b[threadIdx.x]; bk[threadIdx.x] = k_b[threadIdx.x]; }
    __syncthreads();

    {
        const float* fp = s_feat + (size_t)b * C_ * HW_ + h * W_ + w;
        u64 acc[16];
#pragma unroll
        for (int o = 0; o < 16; o++) acc[o] = 0ULL;
#pragma unroll 4
        for (int c = 0; c < C_; c++) {
            float v = fp[(size_t)c * HW_];
            u64 v2; PACK2(v2, v, v);
#pragma unroll
            for (int op = 0; op < 16; op++) FMA2(acc[op], wk[c * 16 + op], v2, acc[op]);
        }
#pragma unroll
        for (int op = 0; op < 16; op++) {
            float lo, hi; UNPK2(lo, hi, acc[op]);
            ksh[(2 * op) * W_ + w]     = lo + bk[2 * op];
            ksh[(2 * op + 1) * W_ + w] = hi + bk[2 * op + 1];
        }
    }

    float qv[CQ_];
    float s1 = 0.f, s2 = 0.f;
    {
        const float* tp = t_feat + (size_t)b * C_ * HW_ + h * W_ + w;
        u64 acc[16];
#pragma unroll
        for (int o = 0; o < 16; o++) acc[o] = 0ULL;
#pragma unroll 4
        for (int c = 0; c < C_; c++) {
            float v = tp[(size_t)c * HW_];
            s1 += v; s2 += v * v;
            u64 v2; PACK2(v2, v, v);
#pragma unroll
            for (int op = 0; op < 16; op++) FMA2(acc[op], wq[c * 16 + op], v2, acc[op]);
        }
        float n2 = 0.f;
#pragma unroll
        for (int op = 0; op < 16; op++) {
            float lo, hi; UNPK2(lo, hi, acc[op]);
            lo += bq[2 * op]; hi += bq[2 * op + 1];
            qv[2 * op] = lo; qv[2 * op + 1] = hi;
            n2 += lo * lo + hi * hi;
        }
        float inv = 1.f / fmaxf(sqrtf(n2), 1e-12f);
#pragma unroll
        for (int c = 0; c < CQ_; c++) qv[c] *= inv;
    }
    __syncthreads();

    float dir = directs[b];
    float* sp = g_sim + (size_t)b * D_ * HW_ + h * W_ + w;
    for (int d = 0; d < D_; d++) {
        float pos = (float)w + disp[d] * dir * (float)(W_ - 1);
        pos = fminf(fmaxf(pos, 0.f), (float)(W_ - 1));
        int x0 = (int)floorf(pos);
        x0 = min(max(x0, 0), W_ - 1);
        int x1 = min(x0 + 1, W_ - 1);
        float t = pos - (float)x0;
        float dot = 0.f, kn2 = 0.f;
#pragma unroll
        for (int c = 0; c < CQ_; c++) {
            float g = ksh[c * W_ + x0] * (1.f - t) + ksh[c * W_ + x1] * t;
            dot += qv[c] * g;
            kn2 += g * g;
        }
        sp[(size_t)d * HW_] = dot / fmaxf(sqrtf(kn2), 1e-12f);
    }

#pragma unroll
    for (int o = 16; o > 0; o >>= 1) {
        s1 += __shfl_xor_sync(0xFFFFFFFFu, s1, o);
        s2 += __shfl_xor_sync(0xFFFFFFFFu, s2, o);
    }
    if (lane == 0) { r1[wrp] = s1; r2[wrp] = s2; }
    __syncthreads();
    if (threadIdx.x == 0) {
        float t1 = 0.f, t2 = 0.f;
#pragma unroll
        for (int i = 0; i < 10; i++) { t1 += r1[i]; t2 += r2[i]; }
        g_partf[((0 * 2 + b) * 480 + h) * 2 + 0] = t1;
        g_partf[((0 * 2 + b) * 480 + h) * 2 + 1] = t2;
    }
}

// ---------------- fused cost filter + softmax + c-stats ----------------
template<int Y>
__device__ __forceinline__ void cost_half(float* cl, const float* __restrict__ base,
                                          const float* __restrict__ wsh,
                                          int h, int w, int lane) {
#pragma unroll
    for (int j = 0; j < 17; j++) {
        const int dd = Y ? (15 + j) : j;
        const int t  = Y ? (j - 1) : j;
        float s0 = 0.f, s1 = 0.f, s2 = 0.f;
#pragma unroll
        for (int r = 0; r < 3; r++) {
            int hh = h + r - 1;
            bool ok = (hh >= 0) && (hh < H_);
            const float* row = base + ((size_t)dd * H_ + hh) * W_;
            float v = ok ? row[w] : 0.f;
            float vm = __shfl_up_sync(0xFFFFFFFFu, v, 1);
            float vp = __shfl_down_sync(0xFFFFFFFFu, v, 1);
            if (lane == 0)  vm = (ok && w > 0)      ? row[w - 1] : 0.f;
            if (lane == 31) vp = (ok && w < W_ - 1) ? row[w + 1] : 0.f;
            s0 += wsh[r * 3 + 0] * vm + wsh[r * 3 + 1] * v + wsh[r * 3 + 2] * vp;
            s1 += wsh[9 + r * 3 + 0] * vm + wsh[9 + r * 3 + 1] * v + wsh[9 + r * 3 + 2] * vp;
            s2 += wsh[18 + r * 3 + 0] * vm + wsh[18 + r * 3 + 1] * v + wsh[18 + r * 3 + 2] * vp;
        }
        if (t + 1 >= 0 && t + 1 < 16 && dd + 1 < D_) cl[t + 1] += s0;
        if (t >= 0 && t < 16)                        cl[t]     += s1;
        if (t - 1 >= 0 && t - 1 < 16)                cl[t - 1] += s2;
    }
}

__global__ void __launch_bounds__(128) k_costsoft(const float* __restrict__ cf_w,
                                                  float* __restrict__ out) {
    __shared__ float wsh[27];
    __shared__ float mx[2][64], sms[2][64];
    __shared__ float r1s[4], r2s[4];
    int h = blockIdx.x / 5, tile = blockIdx.x % 5, b = blockIdx.y;
    int wl = threadIdx.x, y = threadIdx.y;
    int w = tile * 64 + wl;
    int tid = y * 64 + wl;
    int lane = wl & 31;
    if (tid < 27) wsh[tid] = cf_w[tid];
    __syncthreads();

    const float* base = g_sim + (size_t)b * D_ * HW_;
    float cl[16];
#pragma unroll
    for (int j = 0; j < 16; j++) cl[j] = 0.f;
    if (y == 0) cost_half<0>(cl, base, wsh, h, w, lane);
    else        cost_half<1>(cl, base, wsh, h, w, lane);

    float m = -1e30f;
#pragma unroll
    for (int j = 0; j < 16; j++) m = fmaxf(m, cl[j]);
    mx[y][wl] = m;
    __syncthreads();
    m = fmaxf(mx[0][wl], mx[1][wl]);
    float sum = 0.f;
#pragma unroll
    for (int j = 0; j < 16; j++) { cl[j] = expf(cl[j] - m); sum += cl[j]; }
    sms[y][wl] = sum;
    __syncthreads();
    float invs = 1.f / (sms[0][wl] + sms[1][wl]);

    int d0 = y * 16;
    float* op = out + XEL_ + (size_t)b * D_ * HW_ + (size_t)d0 * HW_ + h * W_ + w;
    float ss1 = 0.f, ss2 = 0.f;
#pragma unroll
    for (int j = 0; j < 16; j++) {
        float v = cl[j] * invs;
        op[(size_t)j * HW_] = v;
        ss1 += v; ss2 += v * v;
    }
#pragma unroll
    for (int o = 16; o > 0; o >>= 1) {
        ss1 += __shfl_xor_sync(0xFFFFFFFFu, ss1, o);
        ss2 += __shfl_xor_sync(0xFFFFFFFFu, ss2, o);
    }
    if (lane == 0) { r1s[tid >> 5] = ss1; r2s[tid >> 5] = ss2; }
    __syncthreads();
    if (tid == 0) {
        g_partf[((1 * 2 + b) * 480 + h * 5 + tile) * 2 + 0] = r1s[0] + r1s[1] + r1s[2] + r1s[3];
        g_partf[((1 * 2 + b) * 480 + h * 5 + tile) * 2 + 1] = r2s[0] + r2s[1] + r2s[2] + r2s[3];
    }
}

// ---------------- stats finals (separate tiny kernel) ----------------
__global__ void __launch_bounds__(512) k_statsfinal() {
    __shared__ double sh1[512], sh2[512];
    int which = blockIdx.x >> 1, b = blockIdx.x & 1;
    int n = which ? 480 : 96;
    int t = threadIdx.x;
    double s1 = 0.0, s2 = 0.0;
    if (t < n) {
        s1 = (double)g_partf[((which * 2 + b) * 480 + t) * 2 + 0];
        s2 = (double)g_partf[((which * 2 + b) * 480 + t) * 2 + 1];
    }
    sh1[t] = s1; sh2[t] = s2;
    __syncthreads();
    for (int s = 256; s > 0; s >>= 1) {
        if (t < s) { sh1[t] += sh1[t + s]; sh2[t] += sh2[t + s]; }
        __syncthreads();
    }
    if (t == 0) {
        double N = which ? (double)(D_ * HW_) : (double)(C_ * HW_);
        double mu  = sh1[0] / N;
        double var = sh2[0] / N - mu * mu;
        g_stats[which * 4 + b * 2 + 0] = (float)mu;
        g_stats[which * 4 + b * 2 + 1] = (float)(1.0 / sqrt(var + 1e-5));
    }
}

// ---------------- fuse: GEMM-tiled cost-embed + gating ----------------
#define FS_CN    0
#define FS_CEP   17408
#define FS_FUSED 0
#define FS_ALPHA 34816
#define FS_NCW   35328
#define FS_NCB   35456
#define FS_PROJ  35584
#define FS_FW    35744
#define FS_NTW   36256
#define FS_NTB   36768
#define FS_CEB   37280
#define FUSE_SMEM 37888

__global__ void __launch_bounds__(256) k_fuse(const float* __restrict__ out_base,
                                              const float* __restrict__ t_feat,
                                              const float* __restrict__ nt_w,
                                              const float* __restrict__ nt_b,
                                              const float* __restrict__ nc_w,
                                              const float* __restrict__ nc_b,
                                              const float* __restrict__ ce_w,
                                              const float* __restrict__ ce_b,
                                              const float* __restrict__ fa_b) {
    extern __shared__ __align__(16) char sm[];
    float* cn_s   = reinterpret_cast<float*>(sm + FS_CN);
    float* cep_s  = reinterpret_cast<float*>(sm + FS_CEP);
    __half* fu_s  = reinterpret_cast<__half*>(sm + FS_FUSED);
    float* alp_s  = reinterpret_cast<float*>(sm + FS_ALPHA);
    float* ncw_s  = reinterpret_cast<float*>(sm + FS_NCW);
    float* ncb_s  = reinterpret_cast<float*>(sm + FS_NCB);
    float* proj_s = reinterpret_cast<float*>(sm + FS_PROJ);
    float* fw_s   = reinterpret_cast<float*>(sm + FS_FW);
    float* ntw_s  = reinterpret_cast<float*>(sm + FS_NTW);
    float* ntb_s  = reinterpret_cast<float*>(sm + FS_NTB);
    float* ceb_s  = reinterpret_cast<float*>(sm + FS_CEB);

    int tid = threadIdx.x;
    {
        const float4* cw4 = reinterpret_cast<const float4*>(ce_w);
#pragma unroll
        for (int j = 0; j < 4; j++) {
            int i4 = tid + j * 256;
            float4 v = cw4[i4];
            int base = i4 * 4;
            int oc = base >> 5, d = base & 31;
            cep_s[(d + 0) * 128 + oc] = v.x;
            cep_s[(d + 1) * 128 + oc] = v.y;
            cep_s[(d + 2) * 128 + oc] = v.z;
            cep_s[(d + 3) * 128 + oc] = v.w;
        }
    }
    if (tid < C_) {
        ntw_s[tid] = nt_w[tid];
        ntb_s[tid] = nt_b[tid];
        ceb_s[tid] = ce_b[tid];
        fw_s[tid]  = g_fw[tid];
    }
    if (tid < D_) { ncw_s[tid] = nc_w[tid]; ncb_s[tid] = nc_b[tid]; }
    if (tid >= 128 && tid < 168) proj_s[tid - 128] = g_faproj[tid - 128];
    __syncthreads();

    int blk = blockIdx.x;
    int b = (blk >= 240) ? 1 : 0;
    int pix0 = (blk * 128) % HW_;
    float mu_t = g_stats[b * 2 + 0], inv_t = g_stats[b * 2 + 1];
    float mu_c = g_stats[4 + b * 2 + 0], inv_c = g_stats[4 + b * 2 + 1];

    {
        int pixl = tid >> 1, half = tid & 1;
        int pixg = pix0 + pixl;
        const float* ncp = out_base + XEL_ + (size_t)b * D_ * HW_ + pixg;
        float alin = half ? 0.f
                          : (fa_b[0] + proj_s[32] + proj_s[33] - inv_t * mu_t * proj_s[34]);
#pragma unroll
        for (int j = 0; j < 16; j++) {
            int d = half * 16 + j;
            float v = (ncp[(size_t)d * HW_] - mu_c) * inv_c * ncw_s[d] + ncb_s[d];
            cn_s[d * 136 + pixl] = v;
            alin += proj_s[d] * v;
        }
        const float* tp = t_feat + (size_t)b * C_ * HW_ + pixg;
        float dotft = 0.f;
#pragma unroll 4
        for (int cc = 0; cc < 64; cc++) {
            int c = half * 64 + cc;
            dotft += fw_s[c] * tp[(size_t)c * HW_];
        }
        alin += inv_t * dotft;
        alin += __shfl_xor_sync(0xFFFFFFFFu, alin, 1);
        if (half == 0) alp_s[pixl] = 1.f / (1.f + expf(-alin));
    }
    __syncthreads();

    int tx = tid & 15, ty = tid >> 4;
    int oc0 = ty * 8, px0 = tx * 8;
    float acc[8][8];
#pragma unroll
    for (int o = 0; o < 8; o++) {
        float cb = ceb_s[oc0 + o];
#pragma unroll
        for (int p = 0; p < 8; p++) acc[o][p] = cb;
    }
#pragma unroll 4
    for (int d = 0; d < D_; d++) {
        float4 a0 = *reinterpret_cast<const float4*>(&cep_s[d * 128 + oc0]);
        float4 a1 = *reinterpret_cast<const float4*>(&cep_s[d * 128 + oc0 + 4]);
        float4 b0 = *reinterpret_cast<const float4*>(&cn_s[d * 136 + px0]);
        float4 b1 = *reinterpret_cast<const float4*>(&cn_s[d * 136 + px0 + 4]);
        float av[8] = {a0.x, a0.y, a0.z, a0.w, a1.x, a1.y, a1.z, a1.w};
        float bv[8] = {b0.x, b0.y, b0.z, b0.w, b1.x, b1.y, b1.z, b1.w};
#pragma unroll
        for (int o = 0; o < 8; o++)
#pragma unroll
            for (int p = 0; p < 8; p++) acc[o][p] += av[o] * bv[p];
    }
    __syncthreads();

#pragma unroll
    for (int o = 0; o < 8; o++) {
        int oc = oc0 + o;
        const float* trow = t_feat + (size_t)b * C_ * HW_ + (size_t)oc * HW_ + pix0 + px0;
        float4 t0 = *reinterpret_cast<const float4*>(trow);
        float4 t1 = *reinterpret_cast<const float4*>(trow + 4);
        float tvv[8] = {t0.x, t0.y, t0.z, t0.w, t1.x, t1.y, t1.z, t1.w};
        float wv = ntw_s[oc], bb = ntb_s[oc];
        unsigned hq[4];
#pragma unroll
        for (int p = 0; p < 8; p++) {
            float tv = (tvv[p] - mu_t) * inv_t * wv + bb;
            float al = alp_s[px0 + p];
            float f = al * tv + (1.f - al) * acc[o][p];
            unsigned short us = __half_as_ushort(__float2half_rn(f));
            if ((p & 1) == 0) hq[p >> 1] = us;
            else hq[p >> 1] |= ((unsigned)us << 16);
        }
        *reinterpret_cast<uint4*>(&fu_s[oc * 136 + px0]) = make_uint4(hq[0], hq[1], hq[2], hq[3]);
    }
    __syncthreads();

#pragma unroll
    for (int j = 0; j < 8; j++) {
        int item = tid + j * 256;
        int oc8 = item >> 7;
        int pixl = item & 127;
        int pixg = pix0 + pixl;
        int h = pixg / W_, w = pixg % W_;
        unsigned hq[4];
#pragma unroll
        for (int o = 0; o < 8; o++) {
            unsigned short us = __half_as_ushort(fu_s[(oc8 * 8 + o) * 136 + pixl]);
            if ((o & 1) == 0) hq[o >> 1] = us;
            else hq[o >> 1] |= ((unsigned)us << 16);
        }
        uint4 val = make_uint4(hq[0], hq[1], hq[2], hq[3]);
        size_t pbase = ((size_t)(b * PH_ + h + 1) * PW_ + (w + 1)) * C_ + oc8 * 8;
        *reinterpret_cast<uint4*>(&g_phi[pbase]) = val;
        bool top = (h == 1), bot = (h == H_ - 2);
        bool lef = (w == 1), rig = (w == W_ - 2);
        if (top | bot | lef | rig) {
            const size_t ROW2 = 2 * (size_t)PW_ * C_;
            if (top) *reinterpret_cast<uint4*>(&g_phi[pbase - ROW2]) = val;
            if (bot) *reinterpret_cast<uint4*>(&g_phi[pbase + ROW2]) = val;
            if (lef) *reinterpret_cast<uint4*>(&g_phi[pbase - 2 * C_]) = val;
            if (rig) *reinterpret_cast<uint4*>(&g_phi[pbase + 2 * C_]) = val;
            if (top && lef) *reinterpret_cast<uint4*>(&g_phi[pbase - ROW2 - 2 * C_]) = val;
            if (top && rig) *reinterpret_cast<uint4*>(&g_phi[pbase - ROW2 + 2 * C_]) = val;
            if (bot && lef) *reinterpret_cast<uint4*>(&g_phi[pbase + ROW2 - 2 * C_]) = val;
            if (bot && rig) *reinterpret_cast<uint4*>(&g_phi[pbase + ROW2 + 2 * C_]) = val;
        }
    }
}

// ---------------- mma.sync implicit-GEMM conv (18 iters, K=64) ----------------
#define A_HI  0
#define B_OFF 23040
#define CONV_SMEM 55808

__global__ void __launch_bounds__(256, 2) k_conv_mma(const float* __restrict__ rc_b,
                                                     float* __restrict__ out) {
    extern __shared__ __align__(128) char smem[];
    uint32_t sb = smem_u32(smem);
    int tid = threadIdx.x, lane = tid & 31, wid = tid >> 5;
    int warp_m = wid & 3, warp_n = wid >> 2;

    int bx = blockIdx.x % 20;
    int by = (blockIdx.x / 20) % 12;
    int b  = blockIdx.x / 240;
    int h0 = by * 8, w0 = bx * 16;
    size_t pbase = ((size_t)(b * PH_ + h0) * PW_ + w0) * C_;

    int m_loc = lane & 15, khalf_a = lane >> 4;
    int rA[2], cA[2];
#pragma unroll
    for (int mt = 0; mt < 2; mt++) {
        int m_abs = warp_m * 32 + mt * 16 + m_loc;
        rA[mt] = m_abs >> 4;
        cA[mt] = m_abs & 15;
    }
    int subB = lane >> 3;
    int nl = (lane & 7) + ((subB & 2) << 2);
    int khalf_b = subB & 1;
    uint32_t bRow[4]; int bSw[4];
#pragma unroll
    for (int nb4 = 0; nb4 < 4; nb4++) {
        int oc = warp_n * 64 + nb4 * 16 + nl;
        bRow[nb4] = (uint32_t)oc * 128;
        bSw[nb4]  = oc & 7;
    }

    float acc[2][8][4];
#pragma unroll
    for (int mt = 0; mt < 2; mt++)
#pragma unroll
        for (int n = 0; n < 8; n++)
#pragma unroll
            for (int e = 0; e < 4; e++) acc[mt][n][e] = 0.f;

    {
        const uint4* s0 = reinterpret_cast<const uint4*>(g_wH[0]);
#pragma unroll
        for (int j = 0; j < 4; j++) {
            int idx = tid + j * 256;
            CP16(sb + B_OFF + idx * 16, s0 + idx);
        }
        CP_COMMIT();
    }

    for (int it = 0; it < 18; it++) {
        int chunk = it / 9, tap = it % 9, buf = it & 1;
        int dy = tap / 3, dx = tap % 3;
        __syncthreads();

        if (tap == 0) {
            for (int i = tid; i < 1440; i += 256) {
                int row = i >> 3, ch = i & 7;
                int pr = row / 18, pc = row % 18;
                size_t g = pbase + ((size_t)pr * PW_ + pc) * C_ + chunk * 64 + ch * 8;
                uint32_t so = (uint32_t)row * 128 + ((ch ^ (row & 7)) << 4);
                CP16(sb + A_HI + so, &g_phi[g]);
            }
            CP_COMMIT();
        }
        if (it + 1 < 18) {
            const uint4* s0 = reinterpret_cast<const uint4*>(g_wH[it + 1]);
            uint32_t d0 = sb + B_OFF + (buf ^ 1) * 16384;
#pragma unroll
            for (int j = 0; j < 4; j++) {
                int idx = tid + j * 256;
                CP16(d0 + idx * 16, s0 + idx);
            }
        }
        CP_COMMIT();
        CP_WAIT(1);
        __syncthreads();

        uint32_t bbase = sb + B_OFF + buf * 16384;
        int rowA[2], swA[2];
#pragma unroll
        for (int mt = 0; mt < 2; mt++) {
            rowA[mt] = (rA[mt] + dy) * 18 + cA[mt] + dx;
            swA[mt]  = rowA[mt] & 7;
        }

#pragma unroll
        for (int k16 = 0; k16 < 4; k16++) {
            int chA = k16 * 2 + khalf_a;
            int chB = k16 * 2 + khalf_b;
            uint32_t ah[2][4];
#pragma unroll
            for (int mt = 0; mt < 2; mt++) {
                uint32_t off = (uint32_t)rowA[mt] * 128 + ((chA ^ swA[mt]) << 4);
                ldsm_x4(ah[mt], sb + A_HI + off);
            }
            uint32_t bh[4][4];
#pragma unroll
            for (int nb4 = 0; nb4 < 4; nb4++) {
                uint32_t off = bRow[nb4] + ((chB ^ bSw[nb4]) << 4);
                ldsm_x4(bh[nb4], bbase + off);
            }
#pragma unroll
            for (int mt = 0; mt < 2; mt++) {
#pragma unroll
                for (int nb4 = 0; nb4 < 4; nb4++) {
#pragma unroll
                    for (int half = 0; half < 2; half++) {
                        int n = nb4 * 2 + half;
                        mma16816h(acc[mt][n], ah[mt], bh[nb4][half * 2], bh[nb4][half * 2 + 1]);
                    }
                }
            }
        }
    }

    float* sf = reinterpret_cast<float*>(smem);
    int rbase = lane >> 2, cpair = (lane & 3) * 2;
#pragma unroll
    for (int p = 0; p < 2; p++) {
        __syncthreads();
        if (warp_n == p) {
#pragma unroll
            for (int mt = 0; mt < 2; mt++)
#pragma unroll
                for (int nbl = 0; nbl < 8; nbl++)
#pragma unroll
                    for (int e = 0; e < 4; e++) {
                        int m   = warp_m * 32 + mt * 16 + rbase + ((e >> 1) << 3);
                        int ocl = nbl * 8 + cpair + (e & 1);
                        sf[ocl * 132 + m] = acc[mt][nbl][e];
                    }
        }
        __syncthreads();
#pragma unroll
        for (int j = 0; j < 8; j++) {
            int idx = tid + j * 256;
            int ocl = idx >> 5, q = idx & 31;
            int r = q >> 2, cc = (q & 3) * 4;
            float4 v = *reinterpret_cast<const float4*>(&sf[ocl * 132 + r * 16 + cc]);
            int oc = p * 64 + ocl;
            float bias = rc_b[oc];
            v.x += bias; v.y += bias; v.z += bias; v.w += bias;
            *reinterpret_cast<float4*>(&out[(size_t)(b * C_ + oc) * HW_ + (h0 + r) * W_ + w0 + cc]) = v;
            float s = (v.x + v.y) + (v.z + v.w);
#pragma unroll
            for (int o = 16; o > 0; o >>= 1) s += __shfl_xor_sync(0xFFFFFFFFu, s, o);
            if (lane == 0) g_cpart[(size_t)blockIdx.x * 128 + oc] = s;
        }
    }
}

// ---------------- squeeze-excite ----------------
__global__ void __launch_bounds__(1024) k_se2(const float* __restrict__ se_w1,
                                              const float* __restrict__ se_w2) {
    __shared__ float part[4][256];
    __shared__ float mean_s[256];
    __shared__ float y1s[16];
    int tid = threadIdx.x;
    int q = tid >> 8, bc = tid & 255;
    int b = bc >> 7, c = bc & 127;
    float s = 0.f;
    for (int t = q * 60; t < q * 60 + 60; t++)
        s += g_cpart[(size_t)(b * 240 + t) * 128 + c];
    part[q][bc] = s;
    __syncthreads();
    if (tid < 256) {
        float m = part[0][tid] + part[1][tid] + part[2][tid] + part[3][tid];
        mean_s[tid] = m / (float)HW_;
    }
    __syncthreads();
    if (tid < 16) {
        int bb = tid / 8, j = tid % 8;
        float s2 = 0.f;
        for (int cc = 0; cc < C_; cc++) s2 += mean_s[bb * 128 + cc] * se_w1[j * C_ + cc];
        y1s[tid] = fmaxf(s2, 0.f);
    }
    __syncthreads();
    if (tid < 256) {
        int bb = tid >> 7, cc = tid & 127;
        float s3 = 0.f;
#pragma unroll
        for (int j = 0; j < 8; j++) s3 += y1s[bb * 8 + j] * se_w2[cc * 8 + j];
        g_yscale[tid] = 1.f / (1.f + expf(-s3));
    }
}

__global__ void __launch_bounds__(256) k_elu(float* __restrict__ out) {
    int idx4 = blockIdx.x * 256 + threadIdx.x;
    float ysc = g_yscale[(idx4 * 4) / HW_];
    float4 v = reinterpret_cast<float4*>(out)[idx4];
    v.x *= ysc; v.y *= ysc; v.z *= ysc; v.w *= ysc;
    v.x = v.x > 0.f ? v.x : expm1f(v.x);
    v.y = v.y > 0.f ? v.y : expm1f(v.y);
    v.z = v.z > 0.f ? v.z : expm1f(v.z);
    v.w = v.w > 0.f ? v.w : expm1f(v.w);
    reinterpret_cast<float4*>(out)[idx4] = v;
}

// ---------------- launch ----------------
extern "C" void kernel_launch(void* const* d_in, const int* in_sizes, int n_in,
                              void* d_out, int out_size) {
    const float* t_feat  = (const float*)d_in[0];
    const float* s_feat  = (const float*)d_in[1];
    const float* directs = (const float*)d_in[2];
    const float* disp    = (const float*)d_in[3];
    const float* q_w     = (const float*)d_in[4];
    const float* q_b     = (const float*)d_in[5];
    const float* k_w     = (const float*)d_in[6];
    const float* k_b     = (const float*)d_in[7];
    const float* cf_w    = (const float*)d_in[8];
    const float* nt_w    = (const float*)d_in[10];
    const float* nt_b    = (const float*)d_in[11];
    const float* nc_w    = (const float*)d_in[12];
    const float* nc_b    = (const float*)d_in[13];
    const float* ce_w    = (const float*)d_in[14];
    const float* ce_b    = (const float*)d_in[15];
    const float* fa_w    = (const float*)d_in[16];
    const float* fa_b    = (const float*)d_in[17];
    const float* rc_w    = (const float*)d_in[18];
    const float* rc_b    = (const float*)d_in[19];
    const float* se_w1   = (const float*)d_in[20];
    const float* se_w2   = (const float*)d_in[21];
    float* out = (float*)d_out;

    cudaFuncSetAttribute(k_conv_mma, cudaFuncAttributeMaxDynamicSharedMemorySize, CONV_SMEM);
    cudaFuncSetAttribute(k_simqk, cudaFuncAttributeMaxDynamicSharedMemorySize, SIMQK_SMEM);
    cudaFuncSetAttribute(k_fuse, cudaFuncAttributeMaxDynamicSharedMemorySize, FUSE_SMEM);

    k_prepall<<<19, 256>>>(fa_w, ce_w, ce_b, nt_w, nt_b, rc_w);
    k_simqk<<<dim3(H_, B_), W_, SIMQK_SMEM>>>(t_feat, s_feat, q_w, q_b, k_w, k_b, disp, directs);
    k_costsoft<<<dim3(H_ * 5, B_), dim3(64, 2)>>>(cf_w, out);
    k_statsfinal<<<4, 512>>>();
    k_fuse<<<480, 256, FUSE_SMEM>>>(out, t_feat, nt_w, nt_b, nc_w, nc_b, ce_w, ce_b, fa_b);
    k_conv_mma<<<480, 256, CONV_SMEM>>>(rc_b, out);
    k_se2<<<1, 1024>>>(se_w1, se_w2);
    k_elu<<<XEL_ / 1024, 256>>>(out);
}